// round 1
// baseline (speedup 1.0000x reference)
#include <cuda_runtime.h>
#include <math.h>

// Problem constants (fixed shapes from reference)
#define M_ROWS  32768   // B*S = 16*2048
#define K_DIM   512     // L = E = 512
#define N_CODES 2048    // codebook size

// Scratch (device globals; no allocation allowed)
__device__ float g_zfn [M_ROWS  * K_DIM];   // normalized input projections (64 MB)
__device__ float g_embn[N_CODES * K_DIM];   // normalized codebook (4 MB)
__device__ int   g_idx [M_ROWS];            // argmin indices

// ---------------------------------------------------------------------------
// Row L2-normalize: rows of length 512. One block (128 threads) per row.
// out = in / max(||in||, 1e-12)
// ---------------------------------------------------------------------------
__global__ void rownorm_kernel(const float* __restrict__ in, float* __restrict__ out) {
    int row = blockIdx.x;
    const float4* src = (const float4*)(in + (size_t)row * K_DIM);
    float4 v = src[threadIdx.x];
    float ss = v.x*v.x + v.y*v.y + v.z*v.z + v.w*v.w;
    #pragma unroll
    for (int o = 16; o > 0; o >>= 1) ss += __shfl_down_sync(0xffffffffu, ss, o);
    __shared__ float red[4];
    if ((threadIdx.x & 31) == 0) red[threadIdx.x >> 5] = ss;
    __syncthreads();
    float tot = red[0] + red[1] + red[2] + red[3];
    float inv = 1.0f / fmaxf(sqrtf(tot), 1e-12f);
    v.x *= inv; v.y *= inv; v.z *= inv; v.w *= inv;
    float4* dst = (float4*)(out + (size_t)row * K_DIM);
    dst[threadIdx.x] = v;
}

// ---------------------------------------------------------------------------
// NT SGEMM: C[m][n] = sum_k A[m][k] * B[n][k] (+ bias[n])
// 128x128 tile, BK=16, 256 threads, 8x8 per thread.
// GATHER: A row m is A[gidx[m]] (codebook gather).
// ---------------------------------------------------------------------------
template<bool GATHER, bool BIAS>
__global__ __launch_bounds__(256)
void sgemm_nt_kernel(const float* __restrict__ A, const float* __restrict__ B,
                     const float* __restrict__ bias, const int* __restrict__ gidx,
                     float* __restrict__ C, int N, int K) {
    __shared__ float As[16][132];
    __shared__ float Bs[16][132];
    int tid = threadIdx.x;
    int tx = tid & 15, ty = tid >> 4;
    int rowBase = blockIdx.y * 128;
    int colBase = blockIdx.x * 128;

    float acc[8][8];
    #pragma unroll
    for (int i = 0; i < 8; i++)
        #pragma unroll
        for (int j = 0; j < 8; j++) acc[i][j] = 0.0f;

    for (int kt = 0; kt < K; kt += 16) {
        #pragma unroll
        for (int i = 0; i < 2; i++) {
            int t = tid + i * 256;          // 0..511
            int r  = t >> 2;                // tile row 0..127
            int c4 = t & 3;                 // which float4 of the 16-wide k slice
            int arow = rowBase + r;
            const float* asrc = GATHER ? (A + (size_t)gidx[arow] * K)
                                       : (A + (size_t)arow * K);
            float4 va = *(const float4*)(asrc + kt + c4 * 4);
            As[c4*4+0][r] = va.x; As[c4*4+1][r] = va.y;
            As[c4*4+2][r] = va.z; As[c4*4+3][r] = va.w;
            float4 vb = *(const float4*)(B + (size_t)(colBase + r) * K + kt + c4 * 4);
            Bs[c4*4+0][r] = vb.x; Bs[c4*4+1][r] = vb.y;
            Bs[c4*4+2][r] = vb.z; Bs[c4*4+3][r] = vb.w;
        }
        __syncthreads();
        #pragma unroll
        for (int k = 0; k < 16; k++) {
            float ra[8], rb[8];
            #pragma unroll
            for (int i = 0; i < 8; i++) ra[i] = As[k][ty * 8 + i];
            #pragma unroll
            for (int j = 0; j < 8; j++) rb[j] = Bs[k][tx * 8 + j];
            #pragma unroll
            for (int i = 0; i < 8; i++)
                #pragma unroll
                for (int j = 0; j < 8; j++)
                    acc[i][j] = fmaf(ra[i], rb[j], acc[i][j]);
        }
        __syncthreads();
    }

    #pragma unroll
    for (int i = 0; i < 8; i++) {
        int row = rowBase + ty * 8 + i;
        float* dst = C + (size_t)row * N + colBase + tx * 8;
        #pragma unroll
        for (int j = 0; j < 8; j++) {
            float v = acc[i][j];
            if (BIAS) v += bias[colBase + tx * 8 + j];
            dst[j] = v;
        }
    }
}

// ---------------------------------------------------------------------------
// Fused similarity GEMM + row argmax.
// A = g_zfn (M x 512), B = g_embn (2048 x 512).
// Each block: 128 rows, loops over all 2048 codes in 128-col tiles,
// keeps running argmax (= argmin of negative distance; ties -> lowest index).
// ---------------------------------------------------------------------------
__global__ __launch_bounds__(256)
void argmax_kernel(const float* __restrict__ A, const float* __restrict__ B,
                   int* __restrict__ outIdx) {
    __shared__ float As[16][132];
    __shared__ float Bs[16][132];
    int tid = threadIdx.x;
    int tx = tid & 15, ty = tid >> 4;
    int rowBase = blockIdx.x * 128;

    float best[8];
    int   bidx[8];
    #pragma unroll
    for (int i = 0; i < 8; i++) { best[i] = -1e30f; bidx[i] = 0; }

    for (int nt = 0; nt < N_CODES; nt += 128) {
        float acc[8][8];
        #pragma unroll
        for (int i = 0; i < 8; i++)
            #pragma unroll
            for (int j = 0; j < 8; j++) acc[i][j] = 0.0f;

        for (int kt = 0; kt < K_DIM; kt += 16) {
            #pragma unroll
            for (int i = 0; i < 2; i++) {
                int t = tid + i * 256;
                int r  = t >> 2;
                int c4 = t & 3;
                float4 va = *(const float4*)(A + (size_t)(rowBase + r) * K_DIM + kt + c4 * 4);
                As[c4*4+0][r] = va.x; As[c4*4+1][r] = va.y;
                As[c4*4+2][r] = va.z; As[c4*4+3][r] = va.w;
                float4 vb = *(const float4*)(B + (size_t)(nt + r) * K_DIM + kt + c4 * 4);
                Bs[c4*4+0][r] = vb.x; Bs[c4*4+1][r] = vb.y;
                Bs[c4*4+2][r] = vb.z; Bs[c4*4+3][r] = vb.w;
            }
            __syncthreads();
            #pragma unroll
            for (int k = 0; k < 16; k++) {
                float ra[8], rb[8];
                #pragma unroll
                for (int i = 0; i < 8; i++) ra[i] = As[k][ty * 8 + i];
                #pragma unroll
                for (int j = 0; j < 8; j++) rb[j] = Bs[k][tx * 8 + j];
                #pragma unroll
                for (int i = 0; i < 8; i++)
                    #pragma unroll
                    for (int j = 0; j < 8; j++)
                        acc[i][j] = fmaf(ra[i], rb[j], acc[i][j]);
            }
            __syncthreads();
        }

        // update running best: ascending column order + strict '>' matches
        // argmin-of-negative tie semantics (lowest index wins ties)
        #pragma unroll
        for (int i = 0; i < 8; i++)
            #pragma unroll
            for (int j = 0; j < 8; j++) {
                float v = acc[i][j];
                if (v > best[i]) { best[i] = v; bidx[i] = nt + tx * 8 + j; }
            }
    }

    // cross-thread reduce over the 16 tx threads sharing each row
    __shared__ float sv[16][17];
    __shared__ int   si[16][17];
    for (int i = 0; i < 8; i++) {
        sv[ty][tx] = best[i];
        si[ty][tx] = bidx[i];
        __syncthreads();
        if (tx == 0) {
            float bv = sv[ty][0]; int bi = si[ty][0];
            #pragma unroll
            for (int t = 1; t < 16; t++) {
                // lower tx => lower column index, so strict '>' keeps lowest idx on ties
                if (sv[ty][t] > bv) { bv = sv[ty][t]; bi = si[ty][t]; }
            }
            outIdx[rowBase + ty * 8 + i] = bi;
        }
        __syncthreads();
    }
}

// Indices tail of the output buffer, cast to float (harness output dtype)
__global__ void idx_out_kernel(const int* __restrict__ idx, float* __restrict__ out) {
    int i = blockIdx.x * 256 + threadIdx.x;
    if (i < M_ROWS) out[i] = (float)idx[i];
}

// ---------------------------------------------------------------------------
extern "C" void kernel_launch(void* const* d_in, const int* in_sizes, int n_in,
                              void* d_out, int out_size) {
    // metadata order: z, mask, W_in, b_in, W_out, b_out, emb
    const float* z     = (const float*)d_in[0];
    const float* W_in  = (const float*)d_in[2];
    const float* b_in  = (const float*)d_in[3];
    const float* W_out = (const float*)d_in[4];
    const float* b_out = (const float*)d_in[5];
    const float* emb   = (const float*)d_in[6];
    float* out = (float*)d_out;

    float* zfn;  cudaGetSymbolAddress((void**)&zfn,  g_zfn);
    float* embn; cudaGetSymbolAddress((void**)&embn, g_embn);
    int*   idx;  cudaGetSymbolAddress((void**)&idx,  g_idx);

    // 1) normalize codebook rows: embn = l2norm(emb)
    rownorm_kernel<<<N_CODES, 128>>>(emb, embn);

    // 2) zf = z @ W_in^T + b_in   (M x 512)
    {
        dim3 grid(K_DIM / 128, M_ROWS / 128);
        sgemm_nt_kernel<false, true><<<grid, 256>>>(z, W_in, b_in, nullptr, zfn, K_DIM, K_DIM);
    }

    // 3) zfn = l2norm(zf) in-place
    rownorm_kernel<<<M_ROWS, 128>>>(zfn, zfn);

    // 4) argmax_n <zfn, embn[n]>  (== argmin of negative cosine distance)
    argmax_kernel<<<M_ROWS / 128, 256>>>(zfn, embn, idx);

    // 5) zq = embn[idx] @ W_out^T + b_out  -> output head
    {
        dim3 grid(K_DIM / 128, M_ROWS / 128);
        sgemm_nt_kernel<true, true><<<grid, 256>>>(embn, W_out, b_out, idx, out, K_DIM, K_DIM);
    }

    // 6) indices as float in the output tail (if the buffer includes them)
    if (out_size >= M_ROWS * K_DIM + M_ROWS) {
        idx_out_kernel<<<(M_ROWS + 255) / 256, 256>>>(idx, out + (size_t)M_ROWS * K_DIM);
    }
}

// round 5
// speedup vs baseline: 3.0155x; 3.0155x over previous
#include <cuda_runtime.h>
#include <cuda_bf16.h>
#include <math.h>
#include <stdint.h>

#define M_ROWS 32768
#define KD     512
#define NC     2048

// ---------------- device scratch (static; no allocation) -------------------
__device__ __nv_bfloat16 g_z_hi [M_ROWS*KD];
__device__ __nv_bfloat16 g_z_mid[M_ROWS*KD];
__device__ __nv_bfloat16 g_z_lo [M_ROWS*KD];
__device__ float         g_zf   [M_ROWS*KD];        // zf, then zfn (fp32)
__device__ __nv_bfloat16 g_zfn_hi[M_ROWS*KD];
__device__ float         g_embn  [NC*KD];
__device__ __nv_bfloat16 g_embn_hi[NC*KD];
__device__ __nv_bfloat16 g_embn_lo[NC*KD];
__device__ __nv_bfloat16 g_win_hi [KD*KD], g_win_mid[KD*KD], g_win_lo [KD*KD];
__device__ __nv_bfloat16 g_wout_hi[KD*KD], g_wout_lo[KD*KD];
__device__ float         g_scores[(size_t)M_ROWS*NC];   // 256 MB
__device__ int           g_idx[M_ROWS];

// ---------------- PTX helpers (plain sm_80-era features only) --------------
__device__ __forceinline__ uint32_t smem_u32(const void* p) {
    uint32_t a;
    asm("{ .reg .u64 t; cvta.to.shared.u64 t, %1; cvt.u32.u64 %0, t; }" : "=r"(a) : "l"(p));
    return a;
}
#define CP_ASYNC16(dst, src) \
    asm volatile("cp.async.cg.shared.global [%0], [%1], 16;" :: "r"(dst), "l"(src) : "memory")
#define CP_COMMIT()  asm volatile("cp.async.commit_group;" ::: "memory")
#define CP_WAIT(n)   asm volatile("cp.async.wait_group %0;" :: "n"(n) : "memory")

__device__ __forceinline__ void ldmx4(uint32_t* r, uint32_t addr) {
    asm volatile("ldmatrix.sync.aligned.m8n8.x4.shared.b16 {%0,%1,%2,%3}, [%4];"
                 : "=r"(r[0]), "=r"(r[1]), "=r"(r[2]), "=r"(r[3]) : "r"(addr));
}
__device__ __forceinline__ void mma_bf16(float* c, const uint32_t* a, const uint32_t* b) {
    asm volatile("mma.sync.aligned.m16n8k16.row.col.f32.bf16.bf16.f32 "
                 "{%0,%1,%2,%3}, {%4,%5,%6,%7}, {%8,%9}, {%0,%1,%2,%3};"
                 : "+f"(c[0]), "+f"(c[1]), "+f"(c[2]), "+f"(c[3])
                 : "r"(a[0]), "r"(a[1]), "r"(a[2]), "r"(a[3]), "r"(b[0]), "r"(b[1]));
}

// ---------------- elementwise splits ---------------------------------------
__global__ void split2_kernel(const float* __restrict__ src,
                              __nv_bfloat16* __restrict__ hi,
                              __nv_bfloat16* __restrict__ lo, int n4) {
    for (int i = blockIdx.x * 256 + threadIdx.x; i < n4; i += gridDim.x * 256) {
        float4 v = ((const float4*)src)[i];
        __nv_bfloat16 h[4], l[4];
        float a[4] = {v.x, v.y, v.z, v.w};
        #pragma unroll
        for (int k = 0; k < 4; k++) {
            h[k] = __float2bfloat16_rn(a[k]);
            l[k] = __float2bfloat16_rn(a[k] - __bfloat162float(h[k]));
        }
        ((uint2*)hi)[i] = *(uint2*)h;
        ((uint2*)lo)[i] = *(uint2*)l;
    }
}

__global__ void split3_kernel(const float* __restrict__ src,
                              __nv_bfloat16* __restrict__ hi,
                              __nv_bfloat16* __restrict__ mid,
                              __nv_bfloat16* __restrict__ lo, int n4) {
    for (int i = blockIdx.x * 256 + threadIdx.x; i < n4; i += gridDim.x * 256) {
        float4 v = ((const float4*)src)[i];
        __nv_bfloat16 h[4], m[4], l[4];
        float a[4] = {v.x, v.y, v.z, v.w};
        #pragma unroll
        for (int k = 0; k < 4; k++) {
            h[k] = __float2bfloat16_rn(a[k]);
            float r1 = a[k] - __bfloat162float(h[k]);
            m[k] = __float2bfloat16_rn(r1);
            l[k] = __float2bfloat16_rn(r1 - __bfloat162float(m[k]));
        }
        ((uint2*)hi)[i]  = *(uint2*)h;
        ((uint2*)mid)[i] = *(uint2*)m;
        ((uint2*)lo)[i]  = *(uint2*)l;
    }
}

// ---------------- row L2 normalize + splits --------------------------------
__global__ void rownorm_split_kernel(const float* __restrict__ in,
                                     float* __restrict__ outF,
                                     __nv_bfloat16* __restrict__ hi,
                                     __nv_bfloat16* __restrict__ lo) {
    int row = blockIdx.x;
    const float4* src = (const float4*)(in + (size_t)row * KD);
    float4 v = src[threadIdx.x];
    float ss = v.x*v.x + v.y*v.y + v.z*v.z + v.w*v.w;
    #pragma unroll
    for (int o = 16; o > 0; o >>= 1) ss += __shfl_down_sync(0xffffffffu, ss, o);
    __shared__ float red[4];
    if ((threadIdx.x & 31) == 0) red[threadIdx.x >> 5] = ss;
    __syncthreads();
    float n = fmaxf(sqrtf(red[0] + red[1] + red[2] + red[3]), 1e-12f);
    v.x /= n; v.y /= n; v.z /= n; v.w /= n;
    ((float4*)(outF + (size_t)row * KD))[threadIdx.x] = v;
    float a[4] = {v.x, v.y, v.z, v.w};
    __nv_bfloat16 h[4];
    #pragma unroll
    for (int k = 0; k < 4; k++) h[k] = __float2bfloat16_rn(a[k]);
    *(uint2*)(hi + (size_t)row * KD + threadIdx.x * 4) = *(uint2*)h;
    if (lo) {
        __nv_bfloat16 l[4];
        #pragma unroll
        for (int k = 0; k < 4; k++) l[k] = __float2bfloat16_rn(a[k] - __bfloat162float(h[k]));
        *(uint2*)(lo + (size_t)row * KD + threadIdx.x * 4) = *(uint2*)l;
    }
}

// ---------------- smem tile: 128 rows x 32 bf16, XOR swizzle ---------------
template<bool GATHER>
__device__ __forceinline__ void load_tile_ca(const __nv_bfloat16* __restrict__ src,
                                             const int* __restrict__ gidx,
                                             int rowBase, int kc, uint32_t dstBase, int tid) {
    #pragma unroll
    for (int u = 0; u < 2; u++) {
        int e = tid + u * 256;
        int r = e >> 2, c = e & 3;
        int rg = GATHER ? gidx[rowBase + r] : (rowBase + r);
        const __nv_bfloat16* g = src + (size_t)rg * KD + kc + c * 8;
        uint32_t d = dstBase + r * 64 + ((c ^ ((r >> 1) & 3)) * 16);
        CP_ASYNC16(d, g);
    }
}

// ---------------- one (A-tile, B-tile) MMA contribution --------------------
__device__ __forceinline__ void mma_pair(uint32_t stA, uint32_t stB,
                                         int lane, int warp_m, int warp_n, int ks,
                                         float acc[4][4][4]) {
    uint32_t a[4][4], b[4][2];
    #pragma unroll
    for (int mi = 0; mi < 4; mi++) {
        int row = warp_m * 64 + mi * 16 + (lane & 15);
        int ch  = ks * 2 + (lane >> 4);
        ldmx4(a[mi], stA + row * 64 + ((ch ^ ((row >> 1) & 3)) * 16));
    }
    #pragma unroll
    for (int p = 0; p < 2; p++) {
        int g = lane >> 3;
        int row = warp_n * 32 + p * 16 + ((g & 2) << 2) + (lane & 7);
        int ch  = ks * 2 + (g & 1);
        uint32_t r[4];
        ldmx4(r, stB + row * 64 + ((ch ^ ((row >> 1) & 3)) * 16));
        b[2*p][0] = r[0]; b[2*p][1] = r[1];
        b[2*p+1][0] = r[2]; b[2*p+1][1] = r[3];
    }
    #pragma unroll
    for (int mi = 0; mi < 4; mi++)
        #pragma unroll
        for (int ni = 0; ni < 4; ni++)
            mma_bf16(acc[mi][ni], a[mi], b[ni]);
}

// ---------------- bf16 HMMA GEMM: C = A @ B^T (+bias) ----------------------
// 128x128 CTA tile, BK=32, 8 warps (64x32 warp tile), m16n8k16.
// TERMS: 1 = plain; 3 = hi/lo split (hh,hl,lh); 6 = hi/mid/lo (+mm).
template<int TERMS, bool GATHER, bool BIAS>
__global__ void __launch_bounds__(256) vq_gemm_kernel(
        const __nv_bfloat16* __restrict__ A0, const __nv_bfloat16* __restrict__ A1,
        const __nv_bfloat16* __restrict__ A2,
        const __nv_bfloat16* __restrict__ B0, const __nv_bfloat16* __restrict__ B1,
        const __nv_bfloat16* __restrict__ B2,
        const float* __restrict__ bias, const int* __restrict__ gidx,
        float* __restrict__ C, int Ncols) {
    extern __shared__ char smem[];
    const int NL    = (TERMS == 6) ? 3 : (TERMS == 3) ? 2 : 1;  // split levels
    const int STAGE = NL * 2 * 8192;            // tiles: A0,B0[,A1,B1[,A2,B2]]
    uint32_t sb = smem_u32(smem);
    int tid = threadIdx.x, lane = tid & 31, wid = tid >> 5;
    int warp_m = wid & 1, warp_n = wid >> 1;
    int rowBase = blockIdx.y * 128;
    int colBase = blockIdx.x * 128;

    const __nv_bfloat16* As[3] = {A0, A1, A2};
    const __nv_bfloat16* Bs[3] = {B0, B1, B2};

    float acc[4][4][4];
    #pragma unroll
    for (int mi = 0; mi < 4; mi++)
        #pragma unroll
        for (int ni = 0; ni < 4; ni++)
            #pragma unroll
            for (int q = 0; q < 4; q++) acc[mi][ni][q] = 0.0f;

    // prologue
    #pragma unroll
    for (int l = 0; l < NL; l++) {
        load_tile_ca<GATHER>(As[l], gidx, rowBase, 0, sb + (2*l)   * 8192, tid);
        load_tile_ca<false >(Bs[l], nullptr, colBase, 0, sb + (2*l+1) * 8192, tid);
    }
    CP_COMMIT();

    const int KT = KD / 32;   // 16
    for (int kt = 0; kt < KT; kt++) {
        int s = kt & 1;
        if (kt + 1 < KT) {
            uint32_t st = sb + (s ^ 1) * STAGE;
            int kc = (kt + 1) * 32;
            #pragma unroll
            for (int l = 0; l < NL; l++) {
                load_tile_ca<GATHER>(As[l], gidx, rowBase, kc, st + (2*l)   * 8192, tid);
                load_tile_ca<false >(Bs[l], nullptr, colBase, kc, st + (2*l+1) * 8192, tid);
            }
            CP_COMMIT();
            CP_WAIT(1);
        } else {
            CP_WAIT(0);
        }
        __syncthreads();

        uint32_t st = sb + s * STAGE;
        uint32_t tA[3], tB[3];
        #pragma unroll
        for (int l = 0; l < NL; l++) { tA[l] = st + (2*l)*8192; tB[l] = st + (2*l+1)*8192; }

        #pragma unroll
        for (int ks = 0; ks < 2; ks++) {
            mma_pair(tA[0], tB[0], lane, warp_m, warp_n, ks, acc);          // hh
            if (TERMS >= 3) {
                mma_pair(tA[0], tB[NL-1], lane, warp_m, warp_n, ks, acc);   // h*lo
                mma_pair(tA[NL-1], tB[0], lane, warp_m, warp_n, ks, acc);   // lo*h
            }
            if (TERMS == 6) {
                mma_pair(tA[0], tB[1], lane, warp_m, warp_n, ks, acc);      // hm
                mma_pair(tA[1], tB[0], lane, warp_m, warp_n, ks, acc);      // mh
                mma_pair(tA[1], tB[1], lane, warp_m, warp_n, ks, acc);      // mm
            }
        }
        __syncthreads();
    }

    // epilogue
    #pragma unroll
    for (int mi = 0; mi < 4; mi++) {
        int r0 = rowBase + warp_m * 64 + mi * 16 + (lane >> 2);
        #pragma unroll
        for (int ni = 0; ni < 4; ni++) {
            int col = colBase + warp_n * 32 + ni * 8 + (lane & 3) * 2;
            float b0 = BIAS ? bias[col]     : 0.0f;
            float b1 = BIAS ? bias[col + 1] : 0.0f;
            float2 v0 = {acc[mi][ni][0] + b0, acc[mi][ni][1] + b1};
            float2 v1 = {acc[mi][ni][2] + b0, acc[mi][ni][3] + b1};
            *(float2*)(C + (size_t)r0 * Ncols + col)       = v0;
            *(float2*)(C + (size_t)(r0 + 8) * Ncols + col) = v1;
        }
    }
}

// ---------------- exact fp32 re-rank over fp32 score candidates ------------
__global__ void __launch_bounds__(256) rerank_kernel(
        const float* __restrict__ scores, const float* __restrict__ zfn,
        const float* __restrict__ embn, int* __restrict__ outIdx) {
    int row = blockIdx.x, tid = threadIdx.x;
    __shared__ float srow[KD];
    __shared__ float red[8];
    __shared__ float smax_s, bdot;
    __shared__ int cand[64], ncand, bidx;
    __shared__ float cdot[64];

    const float* sr = scores + (size_t)row * NC;
    float lmax = -1e30f;
    for (int i = tid; i < NC; i += 256) lmax = fmaxf(lmax, sr[i]);
    #pragma unroll
    for (int o = 16; o > 0; o >>= 1) lmax = fmaxf(lmax, __shfl_down_sync(0xffffffffu, lmax, o));
    if ((tid & 31) == 0) red[tid >> 5] = lmax;
    __syncthreads();
    if (tid == 0) {
        float m = red[0];
        #pragma unroll
        for (int w = 1; w < 8; w++) m = fmaxf(m, red[w]);
        smax_s = m; ncand = 0;
    }
    __syncthreads();
    float thr = smax_s - 4e-3f;
    for (int i = tid; i < NC; i += 256)
        if (sr[i] >= thr) {
            int p = atomicAdd(&ncand, 1);
            if (p < 64) cand[p] = i;
        }
    for (int i = tid; i < KD; i += 256) srow[i] = zfn[(size_t)row * KD + i];
    __syncthreads();

    int nc = ncand;
    if (nc <= 64) {
        for (int c = 0; c < nc; c++) {
            const float* e = embn + (size_t)cand[c] * KD;
            float p = srow[tid] * e[tid] + srow[tid + 256] * e[tid + 256];
            #pragma unroll
            for (int o = 16; o > 0; o >>= 1) p += __shfl_down_sync(0xffffffffu, p, o);
            if ((tid & 31) == 0) red[tid >> 5] = p;
            __syncthreads();
            if (tid == 0) {
                float s = 0.f;
                #pragma unroll
                for (int w = 0; w < 8; w++) s += red[w];
                cdot[c] = s;
            }
            __syncthreads();
        }
        if (tid == 0) {
            float best = -1e30f; int bi = NC;
            for (int c = 0; c < nc; c++) {
                float d = cdot[c]; int ci = cand[c];
                if (d > best || (d == best && ci < bi)) { best = d; bi = ci; }
            }
            outIdx[row] = bi;
        }
    } else {
        if (tid == 0) { bdot = -1e30f; bidx = 0; }
        __syncthreads();
        for (int code = 0; code < NC; code++) {
            const float* e = embn + (size_t)code * KD;
            float p = srow[tid] * e[tid] + srow[tid + 256] * e[tid + 256];
            #pragma unroll
            for (int o = 16; o > 0; o >>= 1) p += __shfl_down_sync(0xffffffffu, p, o);
            if ((tid & 31) == 0) red[tid >> 5] = p;
            __syncthreads();
            if (tid == 0) {
                float s = 0.f;
                #pragma unroll
                for (int w = 0; w < 8; w++) s += red[w];
                if (s > bdot) { bdot = s; bidx = code; }
            }
            __syncthreads();
        }
        if (tid == 0) outIdx[row] = bidx;
    }
}

__global__ void idx_out_kernel(const int* __restrict__ idx, float* __restrict__ out) {
    int i = blockIdx.x * 256 + threadIdx.x;
    if (i < M_ROWS) out[i] = (float)idx[i];
}

// ---------------------------------------------------------------------------
extern "C" void kernel_launch(void* const* d_in, const int* in_sizes, int n_in,
                              void* d_out, int out_size) {
    const float* z     = (const float*)d_in[0];
    const float* W_in  = (const float*)d_in[2];
    const float* b_in  = (const float*)d_in[3];
    const float* W_out = (const float*)d_in[4];
    const float* b_out = (const float*)d_in[5];
    const float* emb   = (const float*)d_in[6];
    float* out = (float*)d_out;

    __nv_bfloat16 *z_hi, *z_mid, *z_lo, *zfn_hi, *embn_hi, *embn_lo;
    __nv_bfloat16 *win_hi, *win_mid, *win_lo, *wout_hi, *wout_lo;
    float *zf, *embn, *scores;
    int* idx;
    cudaGetSymbolAddress((void**)&z_hi,   g_z_hi);
    cudaGetSymbolAddress((void**)&z_mid,  g_z_mid);
    cudaGetSymbolAddress((void**)&z_lo,   g_z_lo);
    cudaGetSymbolAddress((void**)&zf,     g_zf);
    cudaGetSymbolAddress((void**)&zfn_hi, g_zfn_hi);
    cudaGetSymbolAddress((void**)&embn,   g_embn);
    cudaGetSymbolAddress((void**)&embn_hi,g_embn_hi);
    cudaGetSymbolAddress((void**)&embn_lo,g_embn_lo);
    cudaGetSymbolAddress((void**)&win_hi, g_win_hi);
    cudaGetSymbolAddress((void**)&win_mid,g_win_mid);
    cudaGetSymbolAddress((void**)&win_lo, g_win_lo);
    cudaGetSymbolAddress((void**)&wout_hi,g_wout_hi);
    cudaGetSymbolAddress((void**)&wout_lo,g_wout_lo);
    cudaGetSymbolAddress((void**)&scores, g_scores);
    cudaGetSymbolAddress((void**)&idx,    g_idx);

    const int SM_T6 = 2 * 6 * 8192;   // 98304
    const int SM_T3 = 2 * 4 * 8192;   // 65536
    const int SM_T1 = 2 * 2 * 8192;   // 32768
    cudaFuncSetAttribute(vq_gemm_kernel<6, false, true >, cudaFuncAttributeMaxDynamicSharedMemorySize, SM_T6);
    cudaFuncSetAttribute(vq_gemm_kernel<1, false, false>, cudaFuncAttributeMaxDynamicSharedMemorySize, SM_T1);
    cudaFuncSetAttribute(vq_gemm_kernel<3, true,  true >, cudaFuncAttributeMaxDynamicSharedMemorySize, SM_T3);

    // 1) splits; normalize codebook (+ 2-way split)
    split3_kernel<<<2048, 256>>>(z, z_hi, z_mid, z_lo, M_ROWS * KD / 4);
    split3_kernel<<<256, 256>>>(W_in, win_hi, win_mid, win_lo, KD * KD / 4);
    split2_kernel<<<256, 256>>>(W_out, wout_hi, wout_lo, KD * KD / 4);
    rownorm_split_kernel<<<NC, 128>>>(emb, embn, embn_hi, embn_lo);

    // 2) zf = z @ W_in^T + b_in   (6-term split: fp32-grade, feeds argmin)
    vq_gemm_kernel<6, false, true><<<dim3(4, 256), 256, SM_T6>>>(
        z_hi, z_mid, z_lo, win_hi, win_mid, win_lo, b_in, nullptr, zf, KD);

    // 3) zfn = l2norm(zf) (fp32 in place) + bf16 hi
    rownorm_split_kernel<<<M_ROWS, 128>>>(zf, zf, zfn_hi, nullptr);

    // 4) bf16 similarity scores (fp32 out) + exact fp32 re-rank
    vq_gemm_kernel<1, false, false><<<dim3(16, 256), 256, SM_T1>>>(
        zfn_hi, nullptr, nullptr, embn_hi, nullptr, nullptr, nullptr, nullptr, scores, NC);
    rerank_kernel<<<M_ROWS, 256>>>(scores, zf, embn, idx);

    // 5) zq = embn[idx] @ W_out^T + b_out  (gather + 3-term split)
    vq_gemm_kernel<3, true, true><<<dim3(4, 256), 256, SM_T3>>>(
        embn_hi, embn_lo, nullptr, wout_hi, wout_lo, nullptr, b_out, idx, out, KD);

    // 6) indices (as float) in output tail
    if (out_size >= M_ROWS * KD + M_ROWS) {
        idx_out_kernel<<<(M_ROWS + 255) / 256, 256>>>(idx, out + (size_t)M_ROWS * KD);
    }
}

// round 7
// speedup vs baseline: 4.1898x; 1.3894x over previous
#include <cuda_runtime.h>
#include <cuda_bf16.h>
#include <math.h>
#include <stdint.h>

#define M_ROWS 32768
#define KD     512
#define NC     2048

// ---------------- device scratch (static; no allocation) -------------------
__device__ __nv_bfloat16 g_z_bf  [M_ROWS*KD];            // bf16(z)
__device__ float         g_embn  [NC*KD];                // normalized codebook fp32
__device__ __nv_bfloat16 g_e_hi[NC*KD], g_e_mid[NC*KD], g_e_lo[NC*KD];
__device__ __nv_bfloat16 g_wt_hi[KD*KD], g_wt_mid[KD*KD], g_wt_lo[KD*KD]; // W_in^T splits
__device__ __nv_bfloat16 g_wout_hi[KD*KD], g_wout_lo[KD*KD];
__device__ float         g_G   [NC*KD];                  // G = embn @ W_in (fp32)
__device__ __nv_bfloat16 g_G_bf[NC*KD];
__device__ float         g_c   [NC];                     // c_n = embn_n . b_in
__device__ __nv_bfloat16 g_scores[(size_t)M_ROWS*NC];    // 128 MB
__device__ int           g_idx[M_ROWS];

// ---------------- PTX helpers (plain sm_80-era features only) --------------
__device__ __forceinline__ uint32_t smem_u32(const void* p) {
    uint32_t a;
    asm("{ .reg .u64 t; cvta.to.shared.u64 t, %1; cvt.u32.u64 %0, t; }" : "=r"(a) : "l"(p));
    return a;
}
#define CP_ASYNC16(dst, src) \
    asm volatile("cp.async.cg.shared.global [%0], [%1], 16;" :: "r"(dst), "l"(src) : "memory")
#define CP_COMMIT()  asm volatile("cp.async.commit_group;" ::: "memory")
#define CP_WAIT(n)   asm volatile("cp.async.wait_group %0;" :: "n"(n) : "memory")

__device__ __forceinline__ void ldmx4(uint32_t* r, uint32_t addr) {
    asm volatile("ldmatrix.sync.aligned.m8n8.x4.shared.b16 {%0,%1,%2,%3}, [%4];"
                 : "=r"(r[0]), "=r"(r[1]), "=r"(r[2]), "=r"(r[3]) : "r"(addr));
}
__device__ __forceinline__ void mma_bf16(float* c, const uint32_t* a, const uint32_t* b) {
    asm volatile("mma.sync.aligned.m16n8k16.row.col.f32.bf16.bf16.f32 "
                 "{%0,%1,%2,%3}, {%4,%5,%6,%7}, {%8,%9}, {%0,%1,%2,%3};"
                 : "+f"(c[0]), "+f"(c[1]), "+f"(c[2]), "+f"(c[3])
                 : "r"(a[0]), "r"(a[1]), "r"(a[2]), "r"(a[3]), "r"(b[0]), "r"(b[1]));
}

// ---------------- small prep kernels ---------------------------------------
__global__ void tobf16_kernel(const float* __restrict__ src,
                              __nv_bfloat16* __restrict__ dst, int n4) {
    for (int i = blockIdx.x * 256 + threadIdx.x; i < n4; i += gridDim.x * 256) {
        float4 v = ((const float4*)src)[i];
        __nv_bfloat16 h[4] = {__float2bfloat16_rn(v.x), __float2bfloat16_rn(v.y),
                              __float2bfloat16_rn(v.z), __float2bfloat16_rn(v.w)};
        ((uint2*)dst)[i] = *(uint2*)h;
    }
}

__global__ void split2_kernel(const float* __restrict__ src,
                              __nv_bfloat16* __restrict__ hi,
                              __nv_bfloat16* __restrict__ lo, int n4) {
    for (int i = blockIdx.x * 256 + threadIdx.x; i < n4; i += gridDim.x * 256) {
        float4 v = ((const float4*)src)[i];
        __nv_bfloat16 h[4], l[4];
        float a[4] = {v.x, v.y, v.z, v.w};
        #pragma unroll
        for (int k = 0; k < 4; k++) {
            h[k] = __float2bfloat16_rn(a[k]);
            l[k] = __float2bfloat16_rn(a[k] - __bfloat162float(h[k]));
        }
        ((uint2*)hi)[i] = *(uint2*)h;
        ((uint2*)lo)[i] = *(uint2*)l;
    }
}

// normalize emb rows -> embn fp32 + 3-way bf16 split
__global__ void rownorm_split3_kernel(const float* __restrict__ in,
                                      float* __restrict__ outF,
                                      __nv_bfloat16* __restrict__ hi,
                                      __nv_bfloat16* __restrict__ mid,
                                      __nv_bfloat16* __restrict__ lo) {
    int row = blockIdx.x;
    float4 v = ((const float4*)(in + (size_t)row * KD))[threadIdx.x];
    float ss = v.x*v.x + v.y*v.y + v.z*v.z + v.w*v.w;
    #pragma unroll
    for (int o = 16; o > 0; o >>= 1) ss += __shfl_down_sync(0xffffffffu, ss, o);
    __shared__ float red[4];
    if ((threadIdx.x & 31) == 0) red[threadIdx.x >> 5] = ss;
    __syncthreads();
    float n = fmaxf(sqrtf(red[0] + red[1] + red[2] + red[3]), 1e-12f);
    v.x /= n; v.y /= n; v.z /= n; v.w /= n;
    ((float4*)(outF + (size_t)row * KD))[threadIdx.x] = v;
    float a[4] = {v.x, v.y, v.z, v.w};
    __nv_bfloat16 h[4], m[4], l[4];
    #pragma unroll
    for (int k = 0; k < 4; k++) {
        h[k] = __float2bfloat16_rn(a[k]);
        float r1 = a[k] - __bfloat162float(h[k]);
        m[k] = __float2bfloat16_rn(r1);
        l[k] = __float2bfloat16_rn(r1 - __bfloat162float(m[k]));
    }
    size_t off = (size_t)row * KD + threadIdx.x * 4;
    *(uint2*)(hi + off)  = *(uint2*)h;
    *(uint2*)(mid + off) = *(uint2*)m;
    *(uint2*)(lo + off)  = *(uint2*)l;
}

// W_in (E,L) -> W_in^T (L,E) with fused 3-way split
__global__ void transpose_split3_kernel(const float* __restrict__ W,
                                        __nv_bfloat16* __restrict__ hi,
                                        __nv_bfloat16* __restrict__ mid,
                                        __nv_bfloat16* __restrict__ lo) {
    __shared__ float t[32][33];
    int bl = blockIdx.x * 32, be = blockIdx.y * 32;
    int tx = threadIdx.x, ty = threadIdx.y;   // 32 x 8
    #pragma unroll
    for (int i = 0; i < 32; i += 8)
        t[ty + i][tx] = W[(size_t)(be + ty + i) * KD + bl + tx];   // t[e_loc][l_loc]
    __syncthreads();
    #pragma unroll
    for (int i = 0; i < 32; i += 8) {
        float a = t[tx][ty + i];               // value W[be+tx][bl+ty+i]
        size_t o = (size_t)(bl + ty + i) * KD + be + tx;  // T[l][e]
        __nv_bfloat16 h = __float2bfloat16_rn(a);
        float r1 = a - __bfloat162float(h);
        __nv_bfloat16 m = __float2bfloat16_rn(r1);
        __nv_bfloat16 l = __float2bfloat16_rn(r1 - __bfloat162float(m));
        hi[o] = h; mid[o] = m; lo[o] = l;
    }
}

// c_n = embn_n . b_in
__global__ void cvec_kernel(const float* __restrict__ embn,
                            const float* __restrict__ b_in, float* __restrict__ c) {
    int n = blockIdx.x, lane = threadIdx.x;
    float s = 0.f;
    for (int i = lane; i < KD; i += 32) s += embn[(size_t)n * KD + i] * b_in[i];
    #pragma unroll
    for (int o = 16; o > 0; o >>= 1) s += __shfl_down_sync(0xffffffffu, s, o);
    if (lane == 0) c[n] = s;
}

// ---------------- smem tile: 128 rows x 32 bf16, XOR swizzle ---------------
template<bool GATHER>
__device__ __forceinline__ void load_tile_ca(const __nv_bfloat16* __restrict__ src,
                                             const int* __restrict__ gidx,
                                             int rowBase, int kc, uint32_t dstBase, int tid) {
    #pragma unroll
    for (int u = 0; u < 2; u++) {
        int e = tid + u * 256;
        int r = e >> 2, c = e & 3;
        int rg = GATHER ? gidx[rowBase + r] : (rowBase + r);
        const __nv_bfloat16* g = src + (size_t)rg * KD + kc + c * 8;
        uint32_t d = dstBase + r * 64 + ((c ^ ((r >> 1) & 3)) * 16);
        CP_ASYNC16(d, g);
    }
}

__device__ __forceinline__ void mma_pair(uint32_t stA, uint32_t stB,
                                         int lane, int warp_m, int warp_n, int ks,
                                         float acc[4][4][4]) {
    uint32_t a[4][4], b[4][2];
    #pragma unroll
    for (int mi = 0; mi < 4; mi++) {
        int row = warp_m * 64 + mi * 16 + (lane & 15);
        int ch  = ks * 2 + (lane >> 4);
        ldmx4(a[mi], stA + row * 64 + ((ch ^ ((row >> 1) & 3)) * 16));
    }
    #pragma unroll
    for (int p = 0; p < 2; p++) {
        int g = lane >> 3;
        int row = warp_n * 32 + p * 16 + ((g & 2) << 2) + (lane & 7);
        int ch  = ks * 2 + (g & 1);
        uint32_t r[4];
        ldmx4(r, stB + row * 64 + ((ch ^ ((row >> 1) & 3)) * 16));
        b[2*p][0] = r[0]; b[2*p][1] = r[1];
        b[2*p+1][0] = r[2]; b[2*p+1][1] = r[3];
    }
    #pragma unroll
    for (int mi = 0; mi < 4; mi++)
        #pragma unroll
        for (int ni = 0; ni < 4; ni++)
            mma_bf16(acc[mi][ni], a[mi], b[ni]);
}

// ---------------- bf16 HMMA GEMM: C = A @ B^T (+bias) ----------------------
// TERMS: 1 plain; 3 = hi/lo (hh,hl,lh); 6 = hi/mid/lo (+hm,mh,mm).
// BF16OUT: store bf16 (scores); else fp32.
template<int TERMS, bool GATHER, bool BIAS, bool BF16OUT>
__global__ void __launch_bounds__(256) vq_gemm_kernel(
        const __nv_bfloat16* __restrict__ A0, const __nv_bfloat16* __restrict__ A1,
        const __nv_bfloat16* __restrict__ A2,
        const __nv_bfloat16* __restrict__ B0, const __nv_bfloat16* __restrict__ B1,
        const __nv_bfloat16* __restrict__ B2,
        const float* __restrict__ bias, const int* __restrict__ gidx,
        float* __restrict__ C, __nv_bfloat16* __restrict__ Sc, int Ncols) {
    extern __shared__ char smem[];
    const int NL    = (TERMS == 6) ? 3 : (TERMS == 3) ? 2 : 1;
    const int STAGE = NL * 2 * 8192;
    uint32_t sb = smem_u32(smem);
    int tid = threadIdx.x, lane = tid & 31, wid = tid >> 5;
    int warp_m = wid & 1, warp_n = wid >> 1;
    int rowBase = blockIdx.y * 128;
    int colBase = blockIdx.x * 128;

    const __nv_bfloat16* As[3] = {A0, A1, A2};
    const __nv_bfloat16* Bs[3] = {B0, B1, B2};

    float acc[4][4][4];
    #pragma unroll
    for (int mi = 0; mi < 4; mi++)
        #pragma unroll
        for (int ni = 0; ni < 4; ni++)
            #pragma unroll
            for (int q = 0; q < 4; q++) acc[mi][ni][q] = 0.0f;

    #pragma unroll
    for (int l = 0; l < NL; l++) {
        load_tile_ca<GATHER>(As[l], gidx, rowBase, 0, sb + (2*l)   * 8192, tid);
        load_tile_ca<false >(Bs[l], nullptr, colBase, 0, sb + (2*l+1) * 8192, tid);
    }
    CP_COMMIT();

    const int KT = KD / 32;
    for (int kt = 0; kt < KT; kt++) {
        int s = kt & 1;
        if (kt + 1 < KT) {
            uint32_t st = sb + (s ^ 1) * STAGE;
            int kc = (kt + 1) * 32;
            #pragma unroll
            for (int l = 0; l < NL; l++) {
                load_tile_ca<GATHER>(As[l], gidx, rowBase, kc, st + (2*l)   * 8192, tid);
                load_tile_ca<false >(Bs[l], nullptr, colBase, kc, st + (2*l+1) * 8192, tid);
            }
            CP_COMMIT();
            CP_WAIT(1);
        } else {
            CP_WAIT(0);
        }
        __syncthreads();

        uint32_t st = sb + s * STAGE;
        uint32_t tA[3], tB[3];
        #pragma unroll
        for (int l = 0; l < NL; l++) { tA[l] = st + (2*l)*8192; tB[l] = st + (2*l+1)*8192; }

        #pragma unroll
        for (int ks = 0; ks < 2; ks++) {
            mma_pair(tA[0], tB[0], lane, warp_m, warp_n, ks, acc);
            if (TERMS >= 3) {
                mma_pair(tA[0], tB[NL-1], lane, warp_m, warp_n, ks, acc);
                mma_pair(tA[NL-1], tB[0], lane, warp_m, warp_n, ks, acc);
            }
            if (TERMS == 6) {
                mma_pair(tA[0], tB[1], lane, warp_m, warp_n, ks, acc);
                mma_pair(tA[1], tB[0], lane, warp_m, warp_n, ks, acc);
                mma_pair(tA[1], tB[1], lane, warp_m, warp_n, ks, acc);
            }
        }
        __syncthreads();
    }

    #pragma unroll
    for (int mi = 0; mi < 4; mi++) {
        int r0 = rowBase + warp_m * 64 + mi * 16 + (lane >> 2);
        #pragma unroll
        for (int ni = 0; ni < 4; ni++) {
            int col = colBase + warp_n * 32 + ni * 8 + (lane & 3) * 2;
            float b0 = BIAS ? bias[col]     : 0.0f;
            float b1 = BIAS ? bias[col + 1] : 0.0f;
            if (BF16OUT) {
                __nv_bfloat162 p0(__float2bfloat16_rn(acc[mi][ni][0] + b0),
                                  __float2bfloat16_rn(acc[mi][ni][1] + b1));
                __nv_bfloat162 p1(__float2bfloat16_rn(acc[mi][ni][2] + b0),
                                  __float2bfloat16_rn(acc[mi][ni][3] + b1));
                *(uint32_t*)(Sc + (size_t)r0 * Ncols + col)       = *(uint32_t*)&p0;
                *(uint32_t*)(Sc + (size_t)(r0 + 8) * Ncols + col) = *(uint32_t*)&p1;
            } else {
                float2 v0 = {acc[mi][ni][0] + b0, acc[mi][ni][1] + b1};
                float2 v1 = {acc[mi][ni][2] + b0, acc[mi][ni][3] + b1};
                *(float2*)(C + (size_t)r0 * Ncols + col)       = v0;
                *(float2*)(C + (size_t)(r0 + 8) * Ncols + col) = v1;
            }
        }
    }
}

// ---------------- exact fp32 re-rank: score = z . G[n] + c[n] --------------
__global__ void __launch_bounds__(256) rerank_kernel(
        const __nv_bfloat16* __restrict__ scores, const float* __restrict__ z,
        const float* __restrict__ G, const float* __restrict__ cvec,
        int* __restrict__ outIdx) {
    int row = blockIdx.x, tid = threadIdx.x;
    __shared__ float srow[KD];
    __shared__ float red[8];
    __shared__ float smax_s, bdot;
    __shared__ int cand[64], ncand, bidx;
    __shared__ float cdot[64];

    const __nv_bfloat16* sr = scores + (size_t)row * NC;
    float lmax = -1e30f;
    for (int i = tid; i < NC; i += 256) lmax = fmaxf(lmax, __bfloat162float(sr[i]));
    #pragma unroll
    for (int o = 16; o > 0; o >>= 1) lmax = fmaxf(lmax, __shfl_down_sync(0xffffffffu, lmax, o));
    if ((tid & 31) == 0) red[tid >> 5] = lmax;
    __syncthreads();
    if (tid == 0) {
        float m = red[0];
        #pragma unroll
        for (int w = 1; w < 8; w++) m = fmaxf(m, red[w]);
        smax_s = m; ncand = 0;
    }
    __syncthreads();
    float thr = smax_s - 0.1f;          // margin >> bf16 mma + storage error
    for (int i = tid; i < NC; i += 256)
        if (__bfloat162float(sr[i]) >= thr) {
            int p = atomicAdd(&ncand, 1);
            if (p < 64) cand[p] = i;
        }
    for (int i = tid; i < KD; i += 256) srow[i] = z[(size_t)row * KD + i];
    __syncthreads();

    int nc = ncand;
    if (nc <= 64) {
        for (int c = 0; c < nc; c++) {
            const float* e = G + (size_t)cand[c] * KD;
            float p = srow[tid] * e[tid] + srow[tid + 256] * e[tid + 256];
            #pragma unroll
            for (int o = 16; o > 0; o >>= 1) p += __shfl_down_sync(0xffffffffu, p, o);
            if ((tid & 31) == 0) red[tid >> 5] = p;
            __syncthreads();
            if (tid == 0) {
                float s = 0.f;
                #pragma unroll
                for (int w = 0; w < 8; w++) s += red[w];
                cdot[c] = s + cvec[cand[c]];
            }
            __syncthreads();
        }
        if (tid == 0) {
            float best = -1e30f; int bi = NC;
            for (int c = 0; c < nc; c++) {
                float d = cdot[c]; int ci = cand[c];
                if (d > best || (d == best && ci < bi)) { best = d; bi = ci; }
            }
            outIdx[row] = bi;
        }
    } else {
        if (tid == 0) { bdot = -1e30f; bidx = 0; }
        __syncthreads();
        for (int code = 0; code < NC; code++) {
            const float* e = G + (size_t)code * KD;
            float p = srow[tid] * e[tid] + srow[tid + 256] * e[tid + 256];
            #pragma unroll
            for (int o = 16; o > 0; o >>= 1) p += __shfl_down_sync(0xffffffffu, p, o);
            if ((tid & 31) == 0) red[tid >> 5] = p;
            __syncthreads();
            if (tid == 0) {
                float s = red[0]+red[1]+red[2]+red[3]+red[4]+red[5]+red[6]+red[7] + cvec[code];
                if (s > bdot) { bdot = s; bidx = code; }
            }
            __syncthreads();
        }
        if (tid == 0) outIdx[row] = bidx;
    }
}

__global__ void idx_out_kernel(const int* __restrict__ idx, float* __restrict__ out) {
    int i = blockIdx.x * 256 + threadIdx.x;
    if (i < M_ROWS) out[i] = (float)idx[i];
}

// ---------------------------------------------------------------------------
extern "C" void kernel_launch(void* const* d_in, const int* in_sizes, int n_in,
                              void* d_out, int out_size) {
    const float* z     = (const float*)d_in[0];
    const float* W_in  = (const float*)d_in[2];
    const float* b_in  = (const float*)d_in[3];
    const float* W_out = (const float*)d_in[4];
    const float* b_out = (const float*)d_in[5];
    const float* emb   = (const float*)d_in[6];
    float* out = (float*)d_out;

    __nv_bfloat16 *z_bf, *e_hi, *e_mid, *e_lo, *wt_hi, *wt_mid, *wt_lo;
    __nv_bfloat16 *wout_hi, *wout_lo, *G_bf, *scores;
    float *embn, *G, *cvec;
    int* idx;
    cudaGetSymbolAddress((void**)&z_bf,   g_z_bf);
    cudaGetSymbolAddress((void**)&embn,   g_embn);
    cudaGetSymbolAddress((void**)&e_hi,   g_e_hi);
    cudaGetSymbolAddress((void**)&e_mid,  g_e_mid);
    cudaGetSymbolAddress((void**)&e_lo,   g_e_lo);
    cudaGetSymbolAddress((void**)&wt_hi,  g_wt_hi);
    cudaGetSymbolAddress((void**)&wt_mid, g_wt_mid);
    cudaGetSymbolAddress((void**)&wt_lo,  g_wt_lo);
    cudaGetSymbolAddress((void**)&wout_hi,g_wout_hi);
    cudaGetSymbolAddress((void**)&wout_lo,g_wout_lo);
    cudaGetSymbolAddress((void**)&G,      g_G);
    cudaGetSymbolAddress((void**)&G_bf,   g_G_bf);
    cudaGetSymbolAddress((void**)&cvec,   g_c);
    cudaGetSymbolAddress((void**)&scores, g_scores);
    cudaGetSymbolAddress((void**)&idx,    g_idx);

    const int SM_T6 = 2 * 6 * 8192;
    const int SM_T3 = 2 * 4 * 8192;
    const int SM_T1 = 2 * 2 * 8192;
    cudaFuncSetAttribute(vq_gemm_kernel<6, false, false, false>, cudaFuncAttributeMaxDynamicSharedMemorySize, SM_T6);
    cudaFuncSetAttribute(vq_gemm_kernel<1, false, true,  true >, cudaFuncAttributeMaxDynamicSharedMemorySize, SM_T1);
    cudaFuncSetAttribute(vq_gemm_kernel<3, true,  true,  false>, cudaFuncAttributeMaxDynamicSharedMemorySize, SM_T3);

    // prep: normalize codebook (+3-way split), W_in^T splits, c vector,
    //       bf16(z), W_out 2-way split
    rownorm_split3_kernel<<<NC, 128>>>(emb, embn, e_hi, e_mid, e_lo);
    transpose_split3_kernel<<<dim3(16, 16), dim3(32, 8)>>>(W_in, wt_hi, wt_mid, wt_lo);
    cvec_kernel<<<NC, 32>>>(embn, b_in, cvec);
    tobf16_kernel<<<2048, 256>>>(z, z_bf, M_ROWS * KD / 4);
    split2_kernel<<<256, 256>>>(W_out, wout_hi, wout_lo, KD * KD / 4);

    // G = embn @ W_in  (fp32-grade via 6-term; tiny: 2048x512x512)
    vq_gemm_kernel<6, false, false, false><<<dim3(4, 16), 256, SM_T6>>>(
        e_hi, e_mid, e_lo, wt_hi, wt_mid, wt_lo, nullptr, nullptr, G, nullptr, KD);
    tobf16_kernel<<<256, 256>>>(G, G_bf, NC * KD / 4);

    // scores = z @ G^T + c  (1-term bf16, bf16 store) ; exact fp32 re-rank
    vq_gemm_kernel<1, false, true, true><<<dim3(16, 256), 256, SM_T1>>>(
        z_bf, nullptr, nullptr, G_bf, nullptr, nullptr, cvec, nullptr,
        nullptr, scores, NC);
    rerank_kernel<<<M_ROWS, 256>>>(scores, z, G, cvec, idx);

    // zq = embn[idx] @ W_out^T + b_out  (gather + 3-term split)
    vq_gemm_kernel<3, true, true, false><<<dim3(4, 256), 256, SM_T3>>>(
        e_hi, e_mid, nullptr, wout_hi, wout_lo, nullptr, b_out, idx,
        out, nullptr, KD);

    // indices (as float) in output tail
    if (out_size >= M_ROWS * KD + M_ROWS) {
        idx_out_kernel<<<(M_ROWS + 255) / 256, 256>>>(idx, out + (size_t)M_ROWS * KD);
    }
}

// round 10
// speedup vs baseline: 5.0900x; 1.2149x over previous
#include <cuda_runtime.h>
#include <cuda_bf16.h>
#include <math.h>
#include <stdint.h>

#define M_ROWS 32768
#define KD     512
#define NC     2048

// ---------------- device scratch (static; no allocation) -------------------
__device__ __nv_bfloat16 g_z_bf  [M_ROWS*KD];            // bf16(z)
__device__ float         g_embn  [NC*KD];                // normalized codebook fp32
__device__ __nv_bfloat16 g_e_hi[NC*KD], g_e_mid[NC*KD], g_e_lo[NC*KD];
__device__ __nv_bfloat16 g_wt_hi[KD*KD], g_wt_mid[KD*KD], g_wt_lo[KD*KD]; // W_in^T splits
__device__ __nv_bfloat16 g_wout_hi[KD*KD], g_wout_lo[KD*KD];
__device__ float         g_G   [NC*KD];                  // G = embn @ W_in (fp32)
__device__ __nv_bfloat16 g_G_bf[NC*KD];
__device__ float         g_c   [NC];                     // c_n = embn_n . b_in
__device__ float         g_table[NC*KD];                 // T = embn @ W_out^T + b_out
__device__ __nv_bfloat16 g_scores[(size_t)M_ROWS*NC];    // 128 MB
__device__ int           g_idx[M_ROWS];

// ---------------- PTX helpers (plain sm_80-era features only) --------------
__device__ __forceinline__ uint32_t smem_u32(const void* p) {
    uint32_t a;
    asm("{ .reg .u64 t; cvta.to.shared.u64 t, %1; cvt.u32.u64 %0, t; }" : "=r"(a) : "l"(p));
    return a;
}
#define CP_ASYNC16(dst, src) \
    asm volatile("cp.async.cg.shared.global [%0], [%1], 16;" :: "r"(dst), "l"(src) : "memory")
#define CP_COMMIT()  asm volatile("cp.async.commit_group;" ::: "memory")
#define CP_WAIT(n)   asm volatile("cp.async.wait_group %0;" :: "n"(n) : "memory")

__device__ __forceinline__ void ldmx4(uint32_t* r, uint32_t addr) {
    asm volatile("ldmatrix.sync.aligned.m8n8.x4.shared.b16 {%0,%1,%2,%3}, [%4];"
                 : "=r"(r[0]), "=r"(r[1]), "=r"(r[2]), "=r"(r[3]) : "r"(addr));
}
__device__ __forceinline__ void mma_bf16(float* c, const uint32_t* a, const uint32_t* b) {
    asm volatile("mma.sync.aligned.m16n8k16.row.col.f32.bf16.bf16.f32 "
                 "{%0,%1,%2,%3}, {%4,%5,%6,%7}, {%8,%9}, {%0,%1,%2,%3};"
                 : "+f"(c[0]), "+f"(c[1]), "+f"(c[2]), "+f"(c[3])
                 : "r"(a[0]), "r"(a[1]), "r"(a[2]), "r"(a[3]), "r"(b[0]), "r"(b[1]));
}

// ---------------- small prep kernels ---------------------------------------
__global__ void tobf16_kernel(const float* __restrict__ src,
                              __nv_bfloat16* __restrict__ dst, int n4) {
    for (int i = blockIdx.x * 256 + threadIdx.x; i < n4; i += gridDim.x * 256) {
        float4 v = ((const float4*)src)[i];
        __nv_bfloat16 h[4] = {__float2bfloat16_rn(v.x), __float2bfloat16_rn(v.y),
                              __float2bfloat16_rn(v.z), __float2bfloat16_rn(v.w)};
        ((uint2*)dst)[i] = *(uint2*)h;
    }
}

__global__ void split2_kernel(const float* __restrict__ src,
                              __nv_bfloat16* __restrict__ hi,
                              __nv_bfloat16* __restrict__ lo, int n4) {
    for (int i = blockIdx.x * 256 + threadIdx.x; i < n4; i += gridDim.x * 256) {
        float4 v = ((const float4*)src)[i];
        __nv_bfloat16 h[4], l[4];
        float a[4] = {v.x, v.y, v.z, v.w};
        #pragma unroll
        for (int k = 0; k < 4; k++) {
            h[k] = __float2bfloat16_rn(a[k]);
            l[k] = __float2bfloat16_rn(a[k] - __bfloat162float(h[k]));
        }
        ((uint2*)hi)[i] = *(uint2*)h;
        ((uint2*)lo)[i] = *(uint2*)l;
    }
}

// normalize emb rows -> embn fp32 + 3-way bf16 split
__global__ void rownorm_split3_kernel(const float* __restrict__ in,
                                      float* __restrict__ outF,
                                      __nv_bfloat16* __restrict__ hi,
                                      __nv_bfloat16* __restrict__ mid,
                                      __nv_bfloat16* __restrict__ lo) {
    int row = blockIdx.x;
    float4 v = ((const float4*)(in + (size_t)row * KD))[threadIdx.x];
    float ss = v.x*v.x + v.y*v.y + v.z*v.z + v.w*v.w;
    #pragma unroll
    for (int o = 16; o > 0; o >>= 1) ss += __shfl_down_sync(0xffffffffu, ss, o);
    __shared__ float red[4];
    if ((threadIdx.x & 31) == 0) red[threadIdx.x >> 5] = ss;
    __syncthreads();
    float n = fmaxf(sqrtf(red[0] + red[1] + red[2] + red[3]), 1e-12f);
    v.x /= n; v.y /= n; v.z /= n; v.w /= n;
    ((float4*)(outF + (size_t)row * KD))[threadIdx.x] = v;
    float a[4] = {v.x, v.y, v.z, v.w};
    __nv_bfloat16 h[4], m[4], l[4];
    #pragma unroll
    for (int k = 0; k < 4; k++) {
        h[k] = __float2bfloat16_rn(a[k]);
        float r1 = a[k] - __bfloat162float(h[k]);
        m[k] = __float2bfloat16_rn(r1);
        l[k] = __float2bfloat16_rn(r1 - __bfloat162float(m[k]));
    }
    size_t off = (size_t)row * KD + threadIdx.x * 4;
    *(uint2*)(hi + off)  = *(uint2*)h;
    *(uint2*)(mid + off) = *(uint2*)m;
    *(uint2*)(lo + off)  = *(uint2*)l;
}

// W_in (E,L) -> W_in^T (L,E) with fused 3-way split
__global__ void transpose_split3_kernel(const float* __restrict__ W,
                                        __nv_bfloat16* __restrict__ hi,
                                        __nv_bfloat16* __restrict__ mid,
                                        __nv_bfloat16* __restrict__ lo) {
    __shared__ float t[32][33];
    int bl = blockIdx.x * 32, be = blockIdx.y * 32;
    int tx = threadIdx.x, ty = threadIdx.y;   // 32 x 8
    #pragma unroll
    for (int i = 0; i < 32; i += 8)
        t[ty + i][tx] = W[(size_t)(be + ty + i) * KD + bl + tx];
    __syncthreads();
    #pragma unroll
    for (int i = 0; i < 32; i += 8) {
        float a = t[tx][ty + i];
        size_t o = (size_t)(bl + ty + i) * KD + be + tx;
        __nv_bfloat16 h = __float2bfloat16_rn(a);
        float r1 = a - __bfloat162float(h);
        __nv_bfloat16 m = __float2bfloat16_rn(r1);
        __nv_bfloat16 l = __float2bfloat16_rn(r1 - __bfloat162float(m));
        hi[o] = h; mid[o] = m; lo[o] = l;
    }
}

// c_n = embn_n . b_in
__global__ void cvec_kernel(const float* __restrict__ embn,
                            const float* __restrict__ b_in, float* __restrict__ c) {
    int n = blockIdx.x, lane = threadIdx.x;
    float s = 0.f;
    for (int i = lane; i < KD; i += 32) s += embn[(size_t)n * KD + i] * b_in[i];
    #pragma unroll
    for (int o = 16; o > 0; o >>= 1) s += __shfl_down_sync(0xffffffffu, s, o);
    if (lane == 0) c[n] = s;
}

// ---------------- smem tile: 128 rows x 32 bf16, XOR swizzle ---------------
__device__ __forceinline__ void load_tile_ca(const __nv_bfloat16* __restrict__ src,
                                             int rowBase, int kc, uint32_t dstBase, int tid) {
    #pragma unroll
    for (int u = 0; u < 2; u++) {
        int e = tid + u * 256;
        int r = e >> 2, c = e & 3;
        const __nv_bfloat16* g = src + (size_t)(rowBase + r) * KD + kc + c * 8;
        uint32_t d = dstBase + r * 64 + ((c ^ ((r >> 1) & 3)) * 16);
        CP_ASYNC16(d, g);
    }
}

__device__ __forceinline__ void mma_pair(uint32_t stA, uint32_t stB,
                                         int lane, int warp_m, int warp_n, int ks,
                                         float acc[4][4][4]) {
    uint32_t a[4][4], b[4][2];
    #pragma unroll
    for (int mi = 0; mi < 4; mi++) {
        int row = warp_m * 64 + mi * 16 + (lane & 15);
        int ch  = ks * 2 + (lane >> 4);
        ldmx4(a[mi], stA + row * 64 + ((ch ^ ((row >> 1) & 3)) * 16));
    }
    #pragma unroll
    for (int p = 0; p < 2; p++) {
        int g = lane >> 3;
        int row = warp_n * 32 + p * 16 + ((g & 2) << 2) + (lane & 7);
        int ch  = ks * 2 + (g & 1);
        uint32_t r[4];
        ldmx4(r, stB + row * 64 + ((ch ^ ((row >> 1) & 3)) * 16));
        b[2*p][0] = r[0]; b[2*p][1] = r[1];
        b[2*p+1][0] = r[2]; b[2*p+1][1] = r[3];
    }
    #pragma unroll
    for (int mi = 0; mi < 4; mi++)
        #pragma unroll
        for (int ni = 0; ni < 4; ni++)
            mma_bf16(acc[mi][ni], a[mi], b[ni]);
}

// ---------------- bf16 HMMA GEMM: C = A @ B^T (+bias) ----------------------
// TERMS: 1 plain; 3 = hi/lo (hh,hl,lh); 6 = hi/mid/lo (+hm,mh,mm).
// BF16OUT: store bf16 (scores); else fp32.
template<int TERMS, bool BIAS, bool BF16OUT>
__global__ void __launch_bounds__(256) vq_gemm_kernel(
        const __nv_bfloat16* __restrict__ A0, const __nv_bfloat16* __restrict__ A1,
        const __nv_bfloat16* __restrict__ A2,
        const __nv_bfloat16* __restrict__ B0, const __nv_bfloat16* __restrict__ B1,
        const __nv_bfloat16* __restrict__ B2,
        const float* __restrict__ bias,
        float* __restrict__ C, __nv_bfloat16* __restrict__ Sc, int Ncols) {
    extern __shared__ char smem[];
    const int NL    = (TERMS == 6) ? 3 : (TERMS == 3) ? 2 : 1;
    const int STAGE = NL * 2 * 8192;
    uint32_t sb = smem_u32(smem);
    int tid = threadIdx.x, lane = tid & 31, wid = tid >> 5;
    int warp_m = wid & 1, warp_n = wid >> 1;
    int rowBase = blockIdx.y * 128;
    int colBase = blockIdx.x * 128;

    const __nv_bfloat16* As[3] = {A0, A1, A2};
    const __nv_bfloat16* Bs[3] = {B0, B1, B2};

    float acc[4][4][4];
    #pragma unroll
    for (int mi = 0; mi < 4; mi++)
        #pragma unroll
        for (int ni = 0; ni < 4; ni++)
            #pragma unroll
            for (int q = 0; q < 4; q++) acc[mi][ni][q] = 0.0f;

    #pragma unroll
    for (int l = 0; l < NL; l++) {
        load_tile_ca(As[l], rowBase, 0, sb + (2*l)   * 8192, tid);
        load_tile_ca(Bs[l], colBase, 0, sb + (2*l+1) * 8192, tid);
    }
    CP_COMMIT();

    const int KT = KD / 32;
    for (int kt = 0; kt < KT; kt++) {
        int s = kt & 1;
        if (kt + 1 < KT) {
            uint32_t st = sb + (s ^ 1) * STAGE;
            int kc = (kt + 1) * 32;
            #pragma unroll
            for (int l = 0; l < NL; l++) {
                load_tile_ca(As[l], rowBase, kc, st + (2*l)   * 8192, tid);
                load_tile_ca(Bs[l], colBase, kc, st + (2*l+1) * 8192, tid);
            }
            CP_COMMIT();
            CP_WAIT(1);
        } else {
            CP_WAIT(0);
        }
        __syncthreads();

        uint32_t st = sb + s * STAGE;
        uint32_t tA[3], tB[3];
        #pragma unroll
        for (int l = 0; l < NL; l++) { tA[l] = st + (2*l)*8192; tB[l] = st + (2*l+1)*8192; }

        #pragma unroll
        for (int ks = 0; ks < 2; ks++) {
            mma_pair(tA[0], tB[0], lane, warp_m, warp_n, ks, acc);
            if (TERMS >= 3) {
                mma_pair(tA[0], tB[NL-1], lane, warp_m, warp_n, ks, acc);
                mma_pair(tA[NL-1], tB[0], lane, warp_m, warp_n, ks, acc);
            }
            if (TERMS == 6) {
                mma_pair(tA[0], tB[1], lane, warp_m, warp_n, ks, acc);
                mma_pair(tA[1], tB[0], lane, warp_m, warp_n, ks, acc);
                mma_pair(tA[1], tB[1], lane, warp_m, warp_n, ks, acc);
            }
        }
        __syncthreads();
    }

    #pragma unroll
    for (int mi = 0; mi < 4; mi++) {
        int r0 = rowBase + warp_m * 64 + mi * 16 + (lane >> 2);
        #pragma unroll
        for (int ni = 0; ni < 4; ni++) {
            int col = colBase + warp_n * 32 + ni * 8 + (lane & 3) * 2;
            float b0 = BIAS ? bias[col]     : 0.0f;
            float b1 = BIAS ? bias[col + 1] : 0.0f;
            if (BF16OUT) {
                __nv_bfloat162 p0(__float2bfloat16_rn(acc[mi][ni][0] + b0),
                                  __float2bfloat16_rn(acc[mi][ni][1] + b1));
                __nv_bfloat162 p1(__float2bfloat16_rn(acc[mi][ni][2] + b0),
                                  __float2bfloat16_rn(acc[mi][ni][3] + b1));
                *(uint32_t*)(Sc + (size_t)r0 * Ncols + col)       = *(uint32_t*)&p0;
                *(uint32_t*)(Sc + (size_t)(r0 + 8) * Ncols + col) = *(uint32_t*)&p1;
            } else {
                float2 v0 = {acc[mi][ni][0] + b0, acc[mi][ni][1] + b1};
                float2 v1 = {acc[mi][ni][2] + b0, acc[mi][ni][3] + b1};
                *(float2*)(C + (size_t)r0 * Ncols + col)       = v0;
                *(float2*)(C + (size_t)(r0 + 8) * Ncols + col) = v1;
            }
        }
    }
}

// ---------------- exact fp32 re-rank: score = z . G[n] + c[n] --------------
__global__ void __launch_bounds__(256) rerank_kernel(
        const __nv_bfloat16* __restrict__ scores, const float* __restrict__ z,
        const float* __restrict__ G, const float* __restrict__ cvec,
        int* __restrict__ outIdx) {
    int row = blockIdx.x, tid = threadIdx.x;
    __shared__ float srow[KD];
    __shared__ float red[8];
    __shared__ float smax_s, bdot;
    __shared__ int cand[64], ncand, bidx;
    __shared__ float cdot[64];

    const __nv_bfloat16* sr = scores + (size_t)row * NC;
    float lmax = -1e30f;
    for (int i = tid; i < NC; i += 256) lmax = fmaxf(lmax, __bfloat162float(sr[i]));
    #pragma unroll
    for (int o = 16; o > 0; o >>= 1) lmax = fmaxf(lmax, __shfl_down_sync(0xffffffffu, lmax, o));
    if ((tid & 31) == 0) red[tid >> 5] = lmax;
    __syncthreads();
    if (tid == 0) {
        float m = red[0];
        #pragma unroll
        for (int w = 1; w < 8; w++) m = fmaxf(m, red[w]);
        smax_s = m; ncand = 0;
    }
    __syncthreads();
    float thr = smax_s - 0.1f;          // margin >> bf16 mma + storage error
    for (int i = tid; i < NC; i += 256)
        if (__bfloat162float(sr[i]) >= thr) {
            int p = atomicAdd(&ncand, 1);
            if (p < 64) cand[p] = i;
        }
    for (int i = tid; i < KD; i += 256) srow[i] = z[(size_t)row * KD + i];
    __syncthreads();

    int nc = ncand;
    if (nc <= 64) {
        for (int c = 0; c < nc; c++) {
            const float* e = G + (size_t)cand[c] * KD;
            float p = srow[tid] * e[tid] + srow[tid + 256] * e[tid + 256];
            #pragma unroll
            for (int o = 16; o > 0; o >>= 1) p += __shfl_down_sync(0xffffffffu, p, o);
            if ((tid & 31) == 0) red[tid >> 5] = p;
            __syncthreads();
            if (tid == 0) {
                float s = 0.f;
                #pragma unroll
                for (int w = 0; w < 8; w++) s += red[w];
                cdot[c] = s + cvec[cand[c]];
            }
            __syncthreads();
        }
        if (tid == 0) {
            float best = -1e30f; int bi = NC;
            for (int c = 0; c < nc; c++) {
                float d = cdot[c]; int ci = cand[c];
                if (d > best || (d == best && ci < bi)) { best = d; bi = ci; }
            }
            outIdx[row] = bi;
        }
    } else {
        if (tid == 0) { bdot = -1e30f; bidx = 0; }
        __syncthreads();
        for (int code = 0; code < NC; code++) {
            const float* e = G + (size_t)code * KD;
            float p = srow[tid] * e[tid] + srow[tid + 256] * e[tid + 256];
            #pragma unroll
            for (int o = 16; o > 0; o >>= 1) p += __shfl_down_sync(0xffffffffu, p, o);
            if ((tid & 31) == 0) red[tid >> 5] = p;
            __syncthreads();
            if (tid == 0) {
                float s = red[0]+red[1]+red[2]+red[3]+red[4]+red[5]+red[6]+red[7] + cvec[code];
                if (s > bdot) { bdot = s; bidx = code; }
            }
            __syncthreads();
        }
        if (tid == 0) outIdx[row] = bidx;
    }
}

// ---------------- output gather: out[m] = table[idx[m]] --------------------
__global__ void __launch_bounds__(256) gather_out_kernel(
        const float* __restrict__ table, const int* __restrict__ idx,
        float* __restrict__ out) {
    // one float4 per thread; 128 float4 per row
    int i = blockIdx.x * 256 + threadIdx.x;
    int m = i >> 7, j = i & 127;
    float4 v = ((const float4*)(table + (size_t)idx[m] * KD))[j];
    ((float4*)(out + (size_t)m * KD))[j] = v;
}

__global__ void idx_out_kernel(const int* __restrict__ idx, float* __restrict__ out) {
    int i = blockIdx.x * 256 + threadIdx.x;
    if (i < M_ROWS) out[i] = (float)idx[i];
}

// ---------------------------------------------------------------------------
extern "C" void kernel_launch(void* const* d_in, const int* in_sizes, int n_in,
                              void* d_out, int out_size) {
    const float* z     = (const float*)d_in[0];
    const float* W_in  = (const float*)d_in[2];
    const float* b_in  = (const float*)d_in[3];
    const float* W_out = (const float*)d_in[4];
    const float* b_out = (const float*)d_in[5];
    const float* emb   = (const float*)d_in[6];
    float* out = (float*)d_out;

    __nv_bfloat16 *z_bf, *e_hi, *e_mid, *e_lo, *wt_hi, *wt_mid, *wt_lo;
    __nv_bfloat16 *wout_hi, *wout_lo, *G_bf, *scores;
    float *embn, *G, *cvec, *table;
    int* idx;
    cudaGetSymbolAddress((void**)&z_bf,   g_z_bf);
    cudaGetSymbolAddress((void**)&embn,   g_embn);
    cudaGetSymbolAddress((void**)&e_hi,   g_e_hi);
    cudaGetSymbolAddress((void**)&e_mid,  g_e_mid);
    cudaGetSymbolAddress((void**)&e_lo,   g_e_lo);
    cudaGetSymbolAddress((void**)&wt_hi,  g_wt_hi);
    cudaGetSymbolAddress((void**)&wt_mid, g_wt_mid);
    cudaGetSymbolAddress((void**)&wt_lo,  g_wt_lo);
    cudaGetSymbolAddress((void**)&wout_hi,g_wout_hi);
    cudaGetSymbolAddress((void**)&wout_lo,g_wout_lo);
    cudaGetSymbolAddress((void**)&G,      g_G);
    cudaGetSymbolAddress((void**)&G_bf,   g_G_bf);
    cudaGetSymbolAddress((void**)&cvec,   g_c);
    cudaGetSymbolAddress((void**)&table,  g_table);
    cudaGetSymbolAddress((void**)&scores, g_scores);
    cudaGetSymbolAddress((void**)&idx,    g_idx);

    const int SM_T6 = 2 * 6 * 8192;
    const int SM_T3 = 2 * 4 * 8192;
    const int SM_T1 = 2 * 2 * 8192;
    cudaFuncSetAttribute(vq_gemm_kernel<6, false, false>, cudaFuncAttributeMaxDynamicSharedMemorySize, SM_T6);
    cudaFuncSetAttribute(vq_gemm_kernel<1, true,  true >, cudaFuncAttributeMaxDynamicSharedMemorySize, SM_T1);
    cudaFuncSetAttribute(vq_gemm_kernel<3, true,  false>, cudaFuncAttributeMaxDynamicSharedMemorySize, SM_T3);

    // prep: normalize codebook (+3-way split), W_in^T splits, c vector,
    //       bf16(z), W_out 2-way split
    rownorm_split3_kernel<<<NC, 128>>>(emb, embn, e_hi, e_mid, e_lo);
    transpose_split3_kernel<<<dim3(16, 16), dim3(32, 8)>>>(W_in, wt_hi, wt_mid, wt_lo);
    cvec_kernel<<<NC, 32>>>(embn, b_in, cvec);
    tobf16_kernel<<<2048, 256>>>(z, z_bf, M_ROWS * KD / 4);
    split2_kernel<<<256, 256>>>(W_out, wout_hi, wout_lo, KD * KD / 4);

    // G = embn @ W_in  (fp32-grade via 6-term; tiny: 2048x512x512)
    vq_gemm_kernel<6, false, false><<<dim3(4, 16), 256, SM_T6>>>(
        e_hi, e_mid, e_lo, wt_hi, wt_mid, wt_lo, nullptr, G, nullptr, KD);
    tobf16_kernel<<<256, 256>>>(G, G_bf, NC * KD / 4);

    // code table T = embn @ W_out^T + b_out
    // A split levels MUST be (hi, mid): hi+mid ~= embn to ~17 bits (e_lo is the
    // negligible residual). R9 bug passed (hi, lo), dropping the 2^-9 mid term.
    vq_gemm_kernel<3, true, false><<<dim3(4, 16), 256, SM_T3>>>(
        e_hi, e_mid, nullptr, wout_hi, wout_lo, nullptr, b_out, table, nullptr, KD);

    // scores = z @ G^T + c  (1-term bf16, bf16 store) ; exact fp32 re-rank
    vq_gemm_kernel<1, true, true><<<dim3(16, 256), 256, SM_T1>>>(
        z_bf, nullptr, nullptr, G_bf, nullptr, nullptr, cvec,
        nullptr, scores, NC);
    rerank_kernel<<<M_ROWS, 256>>>(scores, z, G, cvec, idx);

    // out[m] = table[idx[m]]  (pure gather; same numeric class as R7 zq GEMM)
    gather_out_kernel<<<M_ROWS * KD / 4 / 256, 256>>>(table, idx, out);

    // indices (as float) in output tail
    if (out_size >= M_ROWS * KD + M_ROWS) {
        idx_out_kernel<<<(M_ROWS + 255) / 256, 256>>>(idx, out + (size_t)M_ROWS * KD);
    }
}

// round 11
// speedup vs baseline: 6.9680x; 1.3689x over previous
#include <cuda_runtime.h>
#include <cuda_bf16.h>
#include <math.h>
#include <stdint.h>

#define M_ROWS 32768
#define KD     512
#define NC     2048

// ---------------- device scratch (static; no allocation) -------------------
__device__ __nv_bfloat16 g_z_bf  [M_ROWS*KD];            // bf16(z)
__device__ float         g_embn  [NC*KD];                // normalized codebook fp32
__device__ __nv_bfloat16 g_e_hi[NC*KD], g_e_mid[NC*KD], g_e_lo[NC*KD];
__device__ __nv_bfloat16 g_wt_hi[KD*KD], g_wt_mid[KD*KD], g_wt_lo[KD*KD]; // W_in^T splits
__device__ __nv_bfloat16 g_wout_hi[KD*KD], g_wout_lo[KD*KD];
__device__ float         g_G   [NC*KD];                  // G = embn @ W_in (fp32)
__device__ __nv_bfloat16 g_G_bf[NC*KD];
__device__ float         g_c   [NC];                     // c_n = embn_n . b_in
__device__ float         g_table[NC*KD];                 // T = embn @ W_out^T + b_out
__device__ __nv_bfloat16 g_scores[(size_t)M_ROWS*NC];    // 128 MB
__device__ unsigned      g_rowmax[M_ROWS];               // fenc(max score) per row
__device__ int           g_idx[M_ROWS];

// ---------------- PTX helpers (plain sm_80-era features only) --------------
__device__ __forceinline__ uint32_t smem_u32(const void* p) {
    uint32_t a;
    asm("{ .reg .u64 t; cvta.to.shared.u64 t, %1; cvt.u32.u64 %0, t; }" : "=r"(a) : "l"(p));
    return a;
}
#define CP_ASYNC16(dst, src) \
    asm volatile("cp.async.cg.shared.global [%0], [%1], 16;" :: "r"(dst), "l"(src) : "memory")
#define CP_COMMIT()  asm volatile("cp.async.commit_group;" ::: "memory")
#define CP_WAIT(n)   asm volatile("cp.async.wait_group %0;" :: "n"(n) : "memory")

__device__ __forceinline__ void ldmx4(uint32_t* r, uint32_t addr) {
    asm volatile("ldmatrix.sync.aligned.m8n8.x4.shared.b16 {%0,%1,%2,%3}, [%4];"
                 : "=r"(r[0]), "=r"(r[1]), "=r"(r[2]), "=r"(r[3]) : "r"(addr));
}
__device__ __forceinline__ void mma_bf16(float* c, const uint32_t* a, const uint32_t* b) {
    asm volatile("mma.sync.aligned.m16n8k16.row.col.f32.bf16.bf16.f32 "
                 "{%0,%1,%2,%3}, {%4,%5,%6,%7}, {%8,%9}, {%0,%1,%2,%3};"
                 : "+f"(c[0]), "+f"(c[1]), "+f"(c[2]), "+f"(c[3])
                 : "r"(a[0]), "r"(a[1]), "r"(a[2]), "r"(a[3]), "r"(b[0]), "r"(b[1]));
}

// monotone fp32 <-> uint encoding (for atomicMax over floats)
__device__ __forceinline__ unsigned fenc(float x) {
    unsigned u = __float_as_uint(x);
    return (u & 0x80000000u) ? ~u : (u | 0x80000000u);
}
__device__ __forceinline__ float fdec(unsigned u) {
    u = (u & 0x80000000u) ? (u & 0x7fffffffu) : ~u;
    return __uint_as_float(u);
}

// ---------------- small prep kernels ---------------------------------------
__global__ void tobf16_kernel(const float* __restrict__ src,
                              __nv_bfloat16* __restrict__ dst, int n4) {
    for (int i = blockIdx.x * 256 + threadIdx.x; i < n4; i += gridDim.x * 256) {
        float4 v = ((const float4*)src)[i];
        __nv_bfloat16 h[4] = {__float2bfloat16_rn(v.x), __float2bfloat16_rn(v.y),
                              __float2bfloat16_rn(v.z), __float2bfloat16_rn(v.w)};
        ((uint2*)dst)[i] = *(uint2*)h;
    }
}

__global__ void split2_kernel(const float* __restrict__ src,
                              __nv_bfloat16* __restrict__ hi,
                              __nv_bfloat16* __restrict__ lo, int n4) {
    for (int i = blockIdx.x * 256 + threadIdx.x; i < n4; i += gridDim.x * 256) {
        float4 v = ((const float4*)src)[i];
        __nv_bfloat16 h[4], l[4];
        float a[4] = {v.x, v.y, v.z, v.w};
        #pragma unroll
        for (int k = 0; k < 4; k++) {
            h[k] = __float2bfloat16_rn(a[k]);
            l[k] = __float2bfloat16_rn(a[k] - __bfloat162float(h[k]));
        }
        ((uint2*)hi)[i] = *(uint2*)h;
        ((uint2*)lo)[i] = *(uint2*)l;
    }
}

__global__ void zero_rowmax_kernel(unsigned* __restrict__ r) {
    int i = blockIdx.x * 256 + threadIdx.x;
    if (i < M_ROWS) r[i] = 0u;    // fenc of any finite float is > 0
}

// normalize emb rows -> embn fp32 + 3-way bf16 split
__global__ void rownorm_split3_kernel(const float* __restrict__ in,
                                      float* __restrict__ outF,
                                      __nv_bfloat16* __restrict__ hi,
                                      __nv_bfloat16* __restrict__ mid,
                                      __nv_bfloat16* __restrict__ lo) {
    int row = blockIdx.x;
    float4 v = ((const float4*)(in + (size_t)row * KD))[threadIdx.x];
    float ss = v.x*v.x + v.y*v.y + v.z*v.z + v.w*v.w;
    #pragma unroll
    for (int o = 16; o > 0; o >>= 1) ss += __shfl_down_sync(0xffffffffu, ss, o);
    __shared__ float red[4];
    if ((threadIdx.x & 31) == 0) red[threadIdx.x >> 5] = ss;
    __syncthreads();
    float n = fmaxf(sqrtf(red[0] + red[1] + red[2] + red[3]), 1e-12f);
    v.x /= n; v.y /= n; v.z /= n; v.w /= n;
    ((float4*)(outF + (size_t)row * KD))[threadIdx.x] = v;
    float a[4] = {v.x, v.y, v.z, v.w};
    __nv_bfloat16 h[4], m[4], l[4];
    #pragma unroll
    for (int k = 0; k < 4; k++) {
        h[k] = __float2bfloat16_rn(a[k]);
        float r1 = a[k] - __bfloat162float(h[k]);
        m[k] = __float2bfloat16_rn(r1);
        l[k] = __float2bfloat16_rn(r1 - __bfloat162float(m[k]));
    }
    size_t off = (size_t)row * KD + threadIdx.x * 4;
    *(uint2*)(hi + off)  = *(uint2*)h;
    *(uint2*)(mid + off) = *(uint2*)m;
    *(uint2*)(lo + off)  = *(uint2*)l;
}

// W_in (E,L) -> W_in^T (L,E) with fused 3-way split
__global__ void transpose_split3_kernel(const float* __restrict__ W,
                                        __nv_bfloat16* __restrict__ hi,
                                        __nv_bfloat16* __restrict__ mid,
                                        __nv_bfloat16* __restrict__ lo) {
    __shared__ float t[32][33];
    int bl = blockIdx.x * 32, be = blockIdx.y * 32;
    int tx = threadIdx.x, ty = threadIdx.y;   // 32 x 8
    #pragma unroll
    for (int i = 0; i < 32; i += 8)
        t[ty + i][tx] = W[(size_t)(be + ty + i) * KD + bl + tx];
    __syncthreads();
    #pragma unroll
    for (int i = 0; i < 32; i += 8) {
        float a = t[tx][ty + i];
        size_t o = (size_t)(bl + ty + i) * KD + be + tx;
        __nv_bfloat16 h = __float2bfloat16_rn(a);
        float r1 = a - __bfloat162float(h);
        __nv_bfloat16 m = __float2bfloat16_rn(r1);
        __nv_bfloat16 l = __float2bfloat16_rn(r1 - __bfloat162float(m));
        hi[o] = h; mid[o] = m; lo[o] = l;
    }
}

// c_n = embn_n . b_in
__global__ void cvec_kernel(const float* __restrict__ embn,
                            const float* __restrict__ b_in, float* __restrict__ c) {
    int n = blockIdx.x, lane = threadIdx.x;
    float s = 0.f;
    for (int i = lane; i < KD; i += 32) s += embn[(size_t)n * KD + i] * b_in[i];
    #pragma unroll
    for (int o = 16; o > 0; o >>= 1) s += __shfl_down_sync(0xffffffffu, s, o);
    if (lane == 0) c[n] = s;
}

// ---------------- smem tile: 128 rows x 32 bf16, XOR swizzle ---------------
__device__ __forceinline__ void load_tile_ca(const __nv_bfloat16* __restrict__ src,
                                             int rowBase, int kc, uint32_t dstBase, int tid) {
    #pragma unroll
    for (int u = 0; u < 2; u++) {
        int e = tid + u * 256;
        int r = e >> 2, c = e & 3;
        const __nv_bfloat16* g = src + (size_t)(rowBase + r) * KD + kc + c * 8;
        uint32_t d = dstBase + r * 64 + ((c ^ ((r >> 1) & 3)) * 16);
        CP_ASYNC16(d, g);
    }
}

__device__ __forceinline__ void mma_pair(uint32_t stA, uint32_t stB,
                                         int lane, int warp_m, int warp_n, int ks,
                                         float acc[4][4][4]) {
    uint32_t a[4][4], b[4][2];
    #pragma unroll
    for (int mi = 0; mi < 4; mi++) {
        int row = warp_m * 64 + mi * 16 + (lane & 15);
        int ch  = ks * 2 + (lane >> 4);
        ldmx4(a[mi], stA + row * 64 + ((ch ^ ((row >> 1) & 3)) * 16));
    }
    #pragma unroll
    for (int p = 0; p < 2; p++) {
        int g = lane >> 3;
        int row = warp_n * 32 + p * 16 + ((g & 2) << 2) + (lane & 7);
        int ch  = ks * 2 + (g & 1);
        uint32_t r[4];
        ldmx4(r, stB + row * 64 + ((ch ^ ((row >> 1) & 3)) * 16));
        b[2*p][0] = r[0]; b[2*p][1] = r[1];
        b[2*p+1][0] = r[2]; b[2*p+1][1] = r[3];
    }
    #pragma unroll
    for (int mi = 0; mi < 4; mi++)
        #pragma unroll
        for (int ni = 0; ni < 4; ni++)
            mma_bf16(acc[mi][ni], a[mi], b[ni]);
}

// ---------------- bf16 HMMA GEMM: C = A @ B^T (+bias) ----------------------
// TERMS: 1 plain; 3 = hi/lo (hh,hl,lh); 6 = hi/mid/lo (+hm,mh,mm).
// BF16OUT: store bf16 scores + fused per-row max into rowMax (fenc-encoded).
template<int TERMS, bool BIAS, bool BF16OUT>
__global__ void __launch_bounds__(256) vq_gemm_kernel(
        const __nv_bfloat16* __restrict__ A0, const __nv_bfloat16* __restrict__ A1,
        const __nv_bfloat16* __restrict__ A2,
        const __nv_bfloat16* __restrict__ B0, const __nv_bfloat16* __restrict__ B1,
        const __nv_bfloat16* __restrict__ B2,
        const float* __restrict__ bias,
        float* __restrict__ C, __nv_bfloat16* __restrict__ Sc,
        unsigned* __restrict__ rowMax, int Ncols) {
    extern __shared__ char smem[];
    const int NL    = (TERMS == 6) ? 3 : (TERMS == 3) ? 2 : 1;
    const int STAGE = NL * 2 * 8192;
    uint32_t sb = smem_u32(smem);
    int tid = threadIdx.x, lane = tid & 31, wid = tid >> 5;
    int warp_m = wid & 1, warp_n = wid >> 1;
    int rowBase = blockIdx.y * 128;
    int colBase = blockIdx.x * 128;

    const __nv_bfloat16* As[3] = {A0, A1, A2};
    const __nv_bfloat16* Bs[3] = {B0, B1, B2};

    float acc[4][4][4];
    #pragma unroll
    for (int mi = 0; mi < 4; mi++)
        #pragma unroll
        for (int ni = 0; ni < 4; ni++)
            #pragma unroll
            for (int q = 0; q < 4; q++) acc[mi][ni][q] = 0.0f;

    #pragma unroll
    for (int l = 0; l < NL; l++) {
        load_tile_ca(As[l], rowBase, 0, sb + (2*l)   * 8192, tid);
        load_tile_ca(Bs[l], colBase, 0, sb + (2*l+1) * 8192, tid);
    }
    CP_COMMIT();

    const int KT = KD / 32;
    for (int kt = 0; kt < KT; kt++) {
        int s = kt & 1;
        if (kt + 1 < KT) {
            uint32_t st = sb + (s ^ 1) * STAGE;
            int kc = (kt + 1) * 32;
            #pragma unroll
            for (int l = 0; l < NL; l++) {
                load_tile_ca(As[l], rowBase, kc, st + (2*l)   * 8192, tid);
                load_tile_ca(Bs[l], colBase, kc, st + (2*l+1) * 8192, tid);
            }
            CP_COMMIT();
            CP_WAIT(1);
        } else {
            CP_WAIT(0);
        }
        __syncthreads();

        uint32_t st = sb + s * STAGE;
        uint32_t tA[3], tB[3];
        #pragma unroll
        for (int l = 0; l < NL; l++) { tA[l] = st + (2*l)*8192; tB[l] = st + (2*l+1)*8192; }

        #pragma unroll
        for (int ks = 0; ks < 2; ks++) {
            mma_pair(tA[0], tB[0], lane, warp_m, warp_n, ks, acc);
            if (TERMS >= 3) {
                mma_pair(tA[0], tB[NL-1], lane, warp_m, warp_n, ks, acc);
                mma_pair(tA[NL-1], tB[0], lane, warp_m, warp_n, ks, acc);
            }
            if (TERMS == 6) {
                mma_pair(tA[0], tB[1], lane, warp_m, warp_n, ks, acc);
                mma_pair(tA[1], tB[0], lane, warp_m, warp_n, ks, acc);
                mma_pair(tA[1], tB[1], lane, warp_m, warp_n, ks, acc);
            }
        }
        __syncthreads();
    }

    if (BF16OUT) {
        // reuse tile smem (all warps past final barrier) for per-row max
        unsigned* rmax = (unsigned*)smem;
        if (tid < 128) rmax[tid] = 0u;
        __syncthreads();
        #pragma unroll
        for (int mi = 0; mi < 4; mi++) {
            int rl = warp_m * 64 + mi * 16 + (lane >> 2);
            int r0 = rowBase + rl;
            float m0 = -1e30f, m1 = -1e30f;
            #pragma unroll
            for (int ni = 0; ni < 4; ni++) {
                int col = colBase + warp_n * 32 + ni * 8 + (lane & 3) * 2;
                float b0 = BIAS ? bias[col]     : 0.0f;
                float b1 = BIAS ? bias[col + 1] : 0.0f;
                float v00 = acc[mi][ni][0] + b0, v01 = acc[mi][ni][1] + b1;
                float v10 = acc[mi][ni][2] + b0, v11 = acc[mi][ni][3] + b1;
                __nv_bfloat162 p0(__float2bfloat16_rn(v00), __float2bfloat16_rn(v01));
                __nv_bfloat162 p1(__float2bfloat16_rn(v10), __float2bfloat16_rn(v11));
                *(uint32_t*)(Sc + (size_t)r0 * Ncols + col)       = *(uint32_t*)&p0;
                *(uint32_t*)(Sc + (size_t)(r0 + 8) * Ncols + col) = *(uint32_t*)&p1;
                m0 = fmaxf(m0, fmaxf(v00, v01));
                m1 = fmaxf(m1, fmaxf(v10, v11));
            }
            atomicMax(&rmax[rl],     fenc(m0));
            atomicMax(&rmax[rl + 8], fenc(m1));
        }
        __syncthreads();
        if (tid < 128) atomicMax(&rowMax[rowBase + tid], rmax[tid]);
    } else {
        #pragma unroll
        for (int mi = 0; mi < 4; mi++) {
            int r0 = rowBase + warp_m * 64 + mi * 16 + (lane >> 2);
            #pragma unroll
            for (int ni = 0; ni < 4; ni++) {
                int col = colBase + warp_n * 32 + ni * 8 + (lane & 3) * 2;
                float b0 = BIAS ? bias[col]     : 0.0f;
                float b1 = BIAS ? bias[col + 1] : 0.0f;
                float2 v0 = {acc[mi][ni][0] + b0, acc[mi][ni][1] + b1};
                float2 v1 = {acc[mi][ni][2] + b0, acc[mi][ni][3] + b1};
                *(float2*)(C + (size_t)r0 * Ncols + col)       = v0;
                *(float2*)(C + (size_t)(r0 + 8) * Ncols + col) = v1;
            }
        }
    }
}

// ---------------- exact fp32 re-rank (warp per row) ------------------------
// thr = fused fp32 row max - 0.1 (>> bf16 mma error ~2e-3 + storage ~8e-3).
// Candidates reranked with exact fp32 dot z.G[n] + c[n]; order-independent
// tie rule (d > best) || (d == best && ci < bi) matches argmin-first.
__global__ void __launch_bounds__(256) rerank_kernel(
        const __nv_bfloat16* __restrict__ scores, const float* __restrict__ z,
        const float* __restrict__ G, const float* __restrict__ cvec,
        const unsigned* __restrict__ rowMax, int* __restrict__ outIdx) {
    int warp = threadIdx.x >> 5, lane = threadIdx.x & 31;
    int row = blockIdx.x * 8 + warp;
    __shared__ int s_cnt[8];
    __shared__ int s_cand[8][32];

    const __nv_bfloat16* sr = scores + (size_t)row * NC;
    float thr = fdec(rowMax[row]) - 0.1f;

    float zreg[16];
    const float* zr = z + (size_t)row * KD;
    #pragma unroll
    for (int k = 0; k < 16; k++) zreg[k] = zr[lane + 32 * k];

    if (lane == 0) s_cnt[warp] = 0;
    __syncwarp();

    #pragma unroll
    for (int it = 0; it < 8; it++) {
        uint4 v = ((const uint4*)sr)[it * 32 + lane];
        unsigned wv[4] = {v.x, v.y, v.z, v.w};
        int base = (it * 32 + lane) * 8;
        #pragma unroll
        for (int w2 = 0; w2 < 4; w2++) {
            __nv_bfloat162 p = *(__nv_bfloat162*)&wv[w2];
            float s0 = __bfloat162float(p.x);
            float s1 = __bfloat162float(p.y);
            if (s0 >= thr) { int q = atomicAdd(&s_cnt[warp], 1); if (q < 32) s_cand[warp][q] = base + w2*2; }
            if (s1 >= thr) { int q = atomicAdd(&s_cnt[warp], 1); if (q < 32) s_cand[warp][q] = base + w2*2 + 1; }
        }
    }
    __syncwarp();

    int nc = s_cnt[warp];
    float best = -1e30f; int bi = 0x7fffffff;
    if (nc <= 32) {
        for (int c = 0; c < nc; c++) {
            int ci = s_cand[warp][c];
            const float* g = G + (size_t)ci * KD;
            float d = 0.f;
            #pragma unroll
            for (int k = 0; k < 16; k++) d = fmaf(zreg[k], g[lane + 32 * k], d);
            #pragma unroll
            for (int o = 16; o > 0; o >>= 1) d += __shfl_xor_sync(0xffffffffu, d, o);
            d += cvec[ci];
            if (d > best || (d == best && ci < bi)) { best = d; bi = ci; }
        }
    } else {
        // overflow fallback: exact scan of all codes (ascending, strict >)
        for (int ci = 0; ci < NC; ci++) {
            const float* g = G + (size_t)ci * KD;
            float d = 0.f;
            #pragma unroll
            for (int k = 0; k < 16; k++) d = fmaf(zreg[k], g[lane + 32 * k], d);
            #pragma unroll
            for (int o = 16; o > 0; o >>= 1) d += __shfl_xor_sync(0xffffffffu, d, o);
            d += cvec[ci];
            if (d > best) { best = d; bi = ci; }
        }
    }
    if (lane == 0) outIdx[row] = bi;
}

// ---------------- output gather: out[m] = table[idx[m]] --------------------
__global__ void __launch_bounds__(256) gather_out_kernel(
        const float* __restrict__ table, const int* __restrict__ idx,
        float* __restrict__ out) {
    int i = blockIdx.x * 256 + threadIdx.x;
    int m = i >> 7, j = i & 127;
    float4 v = ((const float4*)(table + (size_t)idx[m] * KD))[j];
    ((float4*)(out + (size_t)m * KD))[j] = v;
}

__global__ void idx_out_kernel(const int* __restrict__ idx, float* __restrict__ out) {
    int i = blockIdx.x * 256 + threadIdx.x;
    if (i < M_ROWS) out[i] = (float)idx[i];
}

// ---------------------------------------------------------------------------
extern "C" void kernel_launch(void* const* d_in, const int* in_sizes, int n_in,
                              void* d_out, int out_size) {
    const float* z     = (const float*)d_in[0];
    const float* W_in  = (const float*)d_in[2];
    const float* b_in  = (const float*)d_in[3];
    const float* W_out = (const float*)d_in[4];
    const float* b_out = (const float*)d_in[5];
    const float* emb   = (const float*)d_in[6];
    float* out = (float*)d_out;

    __nv_bfloat16 *z_bf, *e_hi, *e_mid, *e_lo, *wt_hi, *wt_mid, *wt_lo;
    __nv_bfloat16 *wout_hi, *wout_lo, *G_bf, *scores;
    float *embn, *G, *cvec, *table;
    unsigned* rowmax;
    int* idx;
    cudaGetSymbolAddress((void**)&z_bf,   g_z_bf);
    cudaGetSymbolAddress((void**)&embn,   g_embn);
    cudaGetSymbolAddress((void**)&e_hi,   g_e_hi);
    cudaGetSymbolAddress((void**)&e_mid,  g_e_mid);
    cudaGetSymbolAddress((void**)&e_lo,   g_e_lo);
    cudaGetSymbolAddress((void**)&wt_hi,  g_wt_hi);
    cudaGetSymbolAddress((void**)&wt_mid, g_wt_mid);
    cudaGetSymbolAddress((void**)&wt_lo,  g_wt_lo);
    cudaGetSymbolAddress((void**)&wout_hi,g_wout_hi);
    cudaGetSymbolAddress((void**)&wout_lo,g_wout_lo);
    cudaGetSymbolAddress((void**)&G,      g_G);
    cudaGetSymbolAddress((void**)&G_bf,   g_G_bf);
    cudaGetSymbolAddress((void**)&cvec,   g_c);
    cudaGetSymbolAddress((void**)&table,  g_table);
    cudaGetSymbolAddress((void**)&scores, g_scores);
    cudaGetSymbolAddress((void**)&rowmax, g_rowmax);
    cudaGetSymbolAddress((void**)&idx,    g_idx);

    const int SM_T6 = 2 * 6 * 8192;
    const int SM_T3 = 2 * 4 * 8192;
    const int SM_T1 = 2 * 2 * 8192;
    cudaFuncSetAttribute(vq_gemm_kernel<6, false, false>, cudaFuncAttributeMaxDynamicSharedMemorySize, SM_T6);
    cudaFuncSetAttribute(vq_gemm_kernel<1, true,  true >, cudaFuncAttributeMaxDynamicSharedMemorySize, SM_T1);
    cudaFuncSetAttribute(vq_gemm_kernel<3, true,  false>, cudaFuncAttributeMaxDynamicSharedMemorySize, SM_T3);

    // prep: normalize codebook (+3-way split), W_in^T splits, c vector,
    //       bf16(z), W_out 2-way split, rowmax init
    rownorm_split3_kernel<<<NC, 128>>>(emb, embn, e_hi, e_mid, e_lo);
    transpose_split3_kernel<<<dim3(16, 16), dim3(32, 8)>>>(W_in, wt_hi, wt_mid, wt_lo);
    cvec_kernel<<<NC, 32>>>(embn, b_in, cvec);
    tobf16_kernel<<<2048, 256>>>(z, z_bf, M_ROWS * KD / 4);
    split2_kernel<<<256, 256>>>(W_out, wout_hi, wout_lo, KD * KD / 4);
    zero_rowmax_kernel<<<M_ROWS / 256, 256>>>(rowmax);

    // G = embn @ W_in  (fp32-grade via 6-term; tiny: 2048x512x512)
    vq_gemm_kernel<6, false, false><<<dim3(4, 16), 256, SM_T6>>>(
        e_hi, e_mid, e_lo, wt_hi, wt_mid, wt_lo, nullptr, G, nullptr, nullptr, KD);
    tobf16_kernel<<<256, 256>>>(G, G_bf, NC * KD / 4);

    // code table T = embn @ W_out^T + b_out  (A split = (hi, mid)!)
    vq_gemm_kernel<3, true, false><<<dim3(4, 16), 256, SM_T3>>>(
        e_hi, e_mid, nullptr, wout_hi, wout_lo, nullptr, b_out, table, nullptr, nullptr, KD);

    // scores = z @ G^T + c  (bf16 store + fused fp32 per-row max)
    vq_gemm_kernel<1, true, true><<<dim3(16, 256), 256, SM_T1>>>(
        z_bf, nullptr, nullptr, G_bf, nullptr, nullptr, cvec,
        nullptr, scores, rowmax, NC);

    // warp-per-row exact fp32 re-rank using the fused max
    rerank_kernel<<<M_ROWS / 8, 256>>>(scores, z, G, cvec, rowmax, idx);

    // out[m] = table[idx[m]]
    gather_out_kernel<<<M_ROWS * KD / 4 / 256, 256>>>(table, idx, out);

    // indices (as float) in output tail
    if (out_size >= M_ROWS * KD + M_ROWS) {
        idx_out_kernel<<<(M_ROWS + 255) / 256, 256>>>(idx, out + (size_t)M_ROWS * KD);
    }
}

// round 12
// speedup vs baseline: 7.2928x; 1.0466x over previous
#include <cuda_runtime.h>
#include <cuda_bf16.h>
#include <math.h>
#include <stdint.h>

#define M_ROWS 32768
#define KD     512
#define NC     2048
#define NSLOT  64
#define MARGIN 0.04f

// ---------------- device scratch (static; no allocation) -------------------
__device__ __nv_bfloat16 g_z_bf  [M_ROWS*KD];            // bf16(z)
__device__ float         g_embn  [NC*KD];                // normalized codebook fp32
__device__ __nv_bfloat16 g_e_hi[NC*KD], g_e_mid[NC*KD], g_e_lo[NC*KD];
__device__ __nv_bfloat16 g_wt_hi[KD*KD], g_wt_mid[KD*KD], g_wt_lo[KD*KD]; // W_in^T splits
__device__ __nv_bfloat16 g_wout_hi[KD*KD], g_wout_lo[KD*KD];
__device__ float         g_G   [NC*KD];                  // G = embn @ W_in (fp32)
__device__ __nv_bfloat16 g_G_bf[NC*KD];
__device__ float         g_c   [NC];                     // c_n = embn_n . b_in
__device__ float         g_table[NC*KD];                 // T = embn @ W_out^T + b_out
__device__ unsigned      g_rowmax[M_ROWS];               // fenc(max score) per row
__device__ int           g_ccnt[M_ROWS];                 // candidate counts
__device__ int           g_cand[M_ROWS*NSLOT];           // candidate code ids
__device__ int           g_idx[M_ROWS];

// ---------------- PTX helpers (plain sm_80-era features only) --------------
__device__ __forceinline__ uint32_t smem_u32(const void* p) {
    uint32_t a;
    asm("{ .reg .u64 t; cvta.to.shared.u64 t, %1; cvt.u32.u64 %0, t; }" : "=r"(a) : "l"(p));
    return a;
}
#define CP_ASYNC16(dst, src) \
    asm volatile("cp.async.cg.shared.global [%0], [%1], 16;" :: "r"(dst), "l"(src) : "memory")
#define CP_COMMIT()  asm volatile("cp.async.commit_group;" ::: "memory")
#define CP_WAIT(n)   asm volatile("cp.async.wait_group %0;" :: "n"(n) : "memory")

__device__ __forceinline__ void ldmx4(uint32_t* r, uint32_t addr) {
    asm volatile("ldmatrix.sync.aligned.m8n8.x4.shared.b16 {%0,%1,%2,%3}, [%4];"
                 : "=r"(r[0]), "=r"(r[1]), "=r"(r[2]), "=r"(r[3]) : "r"(addr));
}
__device__ __forceinline__ void mma_bf16(float* c, const uint32_t* a, const uint32_t* b) {
    asm volatile("mma.sync.aligned.m16n8k16.row.col.f32.bf16.bf16.f32 "
                 "{%0,%1,%2,%3}, {%4,%5,%6,%7}, {%8,%9}, {%0,%1,%2,%3};"
                 : "+f"(c[0]), "+f"(c[1]), "+f"(c[2]), "+f"(c[3])
                 : "r"(a[0]), "r"(a[1]), "r"(a[2]), "r"(a[3]), "r"(b[0]), "r"(b[1]));
}

// monotone fp32 <-> uint encoding (for atomicMax over floats)
__device__ __forceinline__ unsigned fenc(float x) {
    unsigned u = __float_as_uint(x);
    return (u & 0x80000000u) ? ~u : (u | 0x80000000u);
}
__device__ __forceinline__ float fdec(unsigned u) {
    u = (u & 0x80000000u) ? (u & 0x7fffffffu) : ~u;
    return __uint_as_float(u);
}

// ---------------- small prep kernels ---------------------------------------
__global__ void tobf16_kernel(const float* __restrict__ src,
                              __nv_bfloat16* __restrict__ dst, int n4) {
    for (int i = blockIdx.x * 256 + threadIdx.x; i < n4; i += gridDim.x * 256) {
        float4 v = ((const float4*)src)[i];
        __nv_bfloat16 h[4] = {__float2bfloat16_rn(v.x), __float2bfloat16_rn(v.y),
                              __float2bfloat16_rn(v.z), __float2bfloat16_rn(v.w)};
        ((uint2*)dst)[i] = *(uint2*)h;
    }
}

__global__ void split2_kernel(const float* __restrict__ src,
                              __nv_bfloat16* __restrict__ hi,
                              __nv_bfloat16* __restrict__ lo, int n4) {
    for (int i = blockIdx.x * 256 + threadIdx.x; i < n4; i += gridDim.x * 256) {
        float4 v = ((const float4*)src)[i];
        __nv_bfloat16 h[4], l[4];
        float a[4] = {v.x, v.y, v.z, v.w};
        #pragma unroll
        for (int k = 0; k < 4; k++) {
            h[k] = __float2bfloat16_rn(a[k]);
            l[k] = __float2bfloat16_rn(a[k] - __bfloat162float(h[k]));
        }
        ((uint2*)hi)[i] = *(uint2*)h;
        ((uint2*)lo)[i] = *(uint2*)l;
    }
}

__global__ void zero_state_kernel(unsigned* __restrict__ r, int* __restrict__ cnt) {
    int i = blockIdx.x * 256 + threadIdx.x;
    if (i < M_ROWS) { r[i] = 0u; cnt[i] = 0; }   // fenc of any finite float > 0
}

// normalize emb rows -> embn fp32 + 3-way bf16 split
__global__ void rownorm_split3_kernel(const float* __restrict__ in,
                                      float* __restrict__ outF,
                                      __nv_bfloat16* __restrict__ hi,
                                      __nv_bfloat16* __restrict__ mid,
                                      __nv_bfloat16* __restrict__ lo) {
    int row = blockIdx.x;
    float4 v = ((const float4*)(in + (size_t)row * KD))[threadIdx.x];
    float ss = v.x*v.x + v.y*v.y + v.z*v.z + v.w*v.w;
    #pragma unroll
    for (int o = 16; o > 0; o >>= 1) ss += __shfl_down_sync(0xffffffffu, ss, o);
    __shared__ float red[4];
    if ((threadIdx.x & 31) == 0) red[threadIdx.x >> 5] = ss;
    __syncthreads();
    float n = fmaxf(sqrtf(red[0] + red[1] + red[2] + red[3]), 1e-12f);
    v.x /= n; v.y /= n; v.z /= n; v.w /= n;
    ((float4*)(outF + (size_t)row * KD))[threadIdx.x] = v;
    float a[4] = {v.x, v.y, v.z, v.w};
    __nv_bfloat16 h[4], m[4], l[4];
    #pragma unroll
    for (int k = 0; k < 4; k++) {
        h[k] = __float2bfloat16_rn(a[k]);
        float r1 = a[k] - __bfloat162float(h[k]);
        m[k] = __float2bfloat16_rn(r1);
        l[k] = __float2bfloat16_rn(r1 - __bfloat162float(m[k]));
    }
    size_t off = (size_t)row * KD + threadIdx.x * 4;
    *(uint2*)(hi + off)  = *(uint2*)h;
    *(uint2*)(mid + off) = *(uint2*)m;
    *(uint2*)(lo + off)  = *(uint2*)l;
}

// W_in (E,L) -> W_in^T (L,E) with fused 3-way split
__global__ void transpose_split3_kernel(const float* __restrict__ W,
                                        __nv_bfloat16* __restrict__ hi,
                                        __nv_bfloat16* __restrict__ mid,
                                        __nv_bfloat16* __restrict__ lo) {
    __shared__ float t[32][33];
    int bl = blockIdx.x * 32, be = blockIdx.y * 32;
    int tx = threadIdx.x, ty = threadIdx.y;   // 32 x 8
    #pragma unroll
    for (int i = 0; i < 32; i += 8)
        t[ty + i][tx] = W[(size_t)(be + ty + i) * KD + bl + tx];
    __syncthreads();
    #pragma unroll
    for (int i = 0; i < 32; i += 8) {
        float a = t[tx][ty + i];
        size_t o = (size_t)(bl + ty + i) * KD + be + tx;
        __nv_bfloat16 h = __float2bfloat16_rn(a);
        float r1 = a - __bfloat162float(h);
        __nv_bfloat16 m = __float2bfloat16_rn(r1);
        __nv_bfloat16 l = __float2bfloat16_rn(r1 - __bfloat162float(m));
        hi[o] = h; mid[o] = m; lo[o] = l;
    }
}

// c_n = embn_n . b_in
__global__ void cvec_kernel(const float* __restrict__ embn,
                            const float* __restrict__ b_in, float* __restrict__ c) {
    int n = blockIdx.x, lane = threadIdx.x;
    float s = 0.f;
    for (int i = lane; i < KD; i += 32) s += embn[(size_t)n * KD + i] * b_in[i];
    #pragma unroll
    for (int o = 16; o > 0; o >>= 1) s += __shfl_down_sync(0xffffffffu, s, o);
    if (lane == 0) c[n] = s;
}

// ---------------- smem tile: 128 rows x 32 bf16, XOR swizzle ---------------
__device__ __forceinline__ void load_tile_ca(const __nv_bfloat16* __restrict__ src,
                                             int rowBase, int kc, uint32_t dstBase, int tid) {
    #pragma unroll
    for (int u = 0; u < 2; u++) {
        int e = tid + u * 256;
        int r = e >> 2, c = e & 3;
        const __nv_bfloat16* g = src + (size_t)(rowBase + r) * KD + kc + c * 8;
        uint32_t d = dstBase + r * 64 + ((c ^ ((r >> 1) & 3)) * 16);
        CP_ASYNC16(d, g);
    }
}

__device__ __forceinline__ void mma_pair(uint32_t stA, uint32_t stB,
                                         int lane, int warp_m, int warp_n, int ks,
                                         float acc[4][4][4]) {
    uint32_t a[4][4], b[4][2];
    #pragma unroll
    for (int mi = 0; mi < 4; mi++) {
        int row = warp_m * 64 + mi * 16 + (lane & 15);
        int ch  = ks * 2 + (lane >> 4);
        ldmx4(a[mi], stA + row * 64 + ((ch ^ ((row >> 1) & 3)) * 16));
    }
    #pragma unroll
    for (int p = 0; p < 2; p++) {
        int g = lane >> 3;
        int row = warp_n * 32 + p * 16 + ((g & 2) << 2) + (lane & 7);
        int ch  = ks * 2 + (g & 1);
        uint32_t r[4];
        ldmx4(r, stB + row * 64 + ((ch ^ ((row >> 1) & 3)) * 16));
        b[2*p][0] = r[0]; b[2*p][1] = r[1];
        b[2*p+1][0] = r[2]; b[2*p+1][1] = r[3];
    }
    #pragma unroll
    for (int mi = 0; mi < 4; mi++)
        #pragma unroll
        for (int ni = 0; ni < 4; ni++)
            mma_bf16(acc[mi][ni], a[mi], b[ni]);
}

// ---------------- bf16 HMMA GEMM: C = A @ B^T (+bias) ----------------------
// TERMS: 1 plain; 3 = hi/lo (hh,hl,lh); 6 = hi/mid/lo (+hm,mh,mm).
// SCORES: no C store; fused per-row max + candidate push (bias = cvec).
//         In SCORES mode N-tiles ride blockIdx.y so one row's CTAs execute in
//         different waves -> later CTAs see a tight global max, few pushes.
template<int TERMS, bool BIAS, bool SCORES>
__global__ void __launch_bounds__(256) vq_gemm_kernel(
        const __nv_bfloat16* __restrict__ A0, const __nv_bfloat16* __restrict__ A1,
        const __nv_bfloat16* __restrict__ A2,
        const __nv_bfloat16* __restrict__ B0, const __nv_bfloat16* __restrict__ B1,
        const __nv_bfloat16* __restrict__ B2,
        const float* __restrict__ bias,
        float* __restrict__ C, unsigned* __restrict__ rowMax,
        int* __restrict__ ccnt, int* __restrict__ cand, int Ncols) {
    extern __shared__ char smem[];
    const int NL    = (TERMS == 6) ? 3 : (TERMS == 3) ? 2 : 1;
    const int STAGE = NL * 2 * 8192;
    uint32_t sb = smem_u32(smem);
    int tid = threadIdx.x, lane = tid & 31, wid = tid >> 5;
    int warp_m = wid & 1, warp_n = wid >> 1;
    int rowBase = (SCORES ? blockIdx.x : blockIdx.y) * 128;
    int colBase = (SCORES ? blockIdx.y : blockIdx.x) * 128;

    const __nv_bfloat16* As[3] = {A0, A1, A2};
    const __nv_bfloat16* Bs[3] = {B0, B1, B2};

    float acc[4][4][4];
    #pragma unroll
    for (int mi = 0; mi < 4; mi++)
        #pragma unroll
        for (int ni = 0; ni < 4; ni++)
            #pragma unroll
            for (int q = 0; q < 4; q++) acc[mi][ni][q] = 0.0f;

    #pragma unroll
    for (int l = 0; l < NL; l++) {
        load_tile_ca(As[l], rowBase, 0, sb + (2*l)   * 8192, tid);
        load_tile_ca(Bs[l], colBase, 0, sb + (2*l+1) * 8192, tid);
    }
    CP_COMMIT();

    const int KT = KD / 32;
    for (int kt = 0; kt < KT; kt++) {
        int s = kt & 1;
        if (kt + 1 < KT) {
            uint32_t st = sb + (s ^ 1) * STAGE;
            int kc = (kt + 1) * 32;
            #pragma unroll
            for (int l = 0; l < NL; l++) {
                load_tile_ca(As[l], rowBase, kc, st + (2*l)   * 8192, tid);
                load_tile_ca(Bs[l], colBase, kc, st + (2*l+1) * 8192, tid);
            }
            CP_COMMIT();
            CP_WAIT(1);
        } else {
            CP_WAIT(0);
        }
        __syncthreads();

        uint32_t st = sb + s * STAGE;
        uint32_t tA[3], tB[3];
        #pragma unroll
        for (int l = 0; l < NL; l++) { tA[l] = st + (2*l)*8192; tB[l] = st + (2*l+1)*8192; }

        #pragma unroll
        for (int ks = 0; ks < 2; ks++) {
            mma_pair(tA[0], tB[0], lane, warp_m, warp_n, ks, acc);
            if (TERMS >= 3) {
                mma_pair(tA[0], tB[NL-1], lane, warp_m, warp_n, ks, acc);
                mma_pair(tA[NL-1], tB[0], lane, warp_m, warp_n, ks, acc);
            }
            if (TERMS == 6) {
                mma_pair(tA[0], tB[1], lane, warp_m, warp_n, ks, acc);
                mma_pair(tA[1], tB[0], lane, warp_m, warp_n, ks, acc);
                mma_pair(tA[1], tB[1], lane, warp_m, warp_n, ks, acc);
            }
        }
        __syncthreads();
    }

    if (SCORES) {
        // add bias into registers (scores = acc + c[col])
        #pragma unroll
        for (int ni = 0; ni < 4; ni++) {
            int col = colBase + warp_n * 32 + ni * 8 + (lane & 3) * 2;
            float b0 = bias[col], b1 = bias[col + 1];
            #pragma unroll
            for (int mi = 0; mi < 4; mi++) {
                acc[mi][ni][0] += b0; acc[mi][ni][1] += b1;
                acc[mi][ni][2] += b0; acc[mi][ni][3] += b1;
            }
        }
        // block-level per-row max (reuse tile smem; all warps past final barrier)
        unsigned* rmax = (unsigned*)smem;
        if (tid < 128) rmax[tid] = 0u;
        __syncthreads();
        #pragma unroll
        for (int mi = 0; mi < 4; mi++) {
            int rl = warp_m * 64 + mi * 16 + (lane >> 2);
            float m0 = -1e30f, m1 = -1e30f;
            #pragma unroll
            for (int ni = 0; ni < 4; ni++) {
                m0 = fmaxf(m0, fmaxf(acc[mi][ni][0], acc[mi][ni][1]));
                m1 = fmaxf(m1, fmaxf(acc[mi][ni][2], acc[mi][ni][3]));
            }
            atomicMax(&rmax[rl],     fenc(m0));
            atomicMax(&rmax[rl + 8], fenc(m1));
        }
        __syncthreads();
        // one global atomic per row; write back current best-known max
        if (tid < 128) {
            unsigned mine = rmax[tid];
            unsigned old = atomicMax(&rowMax[rowBase + tid], mine);
            rmax[tid] = (old > mine) ? old : mine;
        }
        __syncthreads();
        // push candidates >= current_max - MARGIN (superset of true set)
        #pragma unroll
        for (int mi = 0; mi < 4; mi++) {
            int rl = warp_m * 64 + mi * 16 + (lane >> 2);
            int r0 = rowBase + rl, r1 = r0 + 8;
            float t0 = fdec(rmax[rl]) - MARGIN;
            float t1 = fdec(rmax[rl + 8]) - MARGIN;
            #pragma unroll
            for (int ni = 0; ni < 4; ni++) {
                int col = colBase + warp_n * 32 + ni * 8 + (lane & 3) * 2;
                if (acc[mi][ni][0] >= t0) { int q = atomicAdd(&ccnt[r0], 1); if (q < NSLOT) cand[r0*NSLOT+q] = col; }
                if (acc[mi][ni][1] >= t0) { int q = atomicAdd(&ccnt[r0], 1); if (q < NSLOT) cand[r0*NSLOT+q] = col+1; }
                if (acc[mi][ni][2] >= t1) { int q = atomicAdd(&ccnt[r1], 1); if (q < NSLOT) cand[r1*NSLOT+q] = col; }
                if (acc[mi][ni][3] >= t1) { int q = atomicAdd(&ccnt[r1], 1); if (q < NSLOT) cand[r1*NSLOT+q] = col+1; }
            }
        }
    } else {
        #pragma unroll
        for (int mi = 0; mi < 4; mi++) {
            int r0 = rowBase + warp_m * 64 + mi * 16 + (lane >> 2);
            #pragma unroll
            for (int ni = 0; ni < 4; ni++) {
                int col = colBase + warp_n * 32 + ni * 8 + (lane & 3) * 2;
                float b0 = BIAS ? bias[col]     : 0.0f;
                float b1 = BIAS ? bias[col + 1] : 0.0f;
                float2 v0 = {acc[mi][ni][0] + b0, acc[mi][ni][1] + b1};
                float2 v1 = {acc[mi][ni][2] + b0, acc[mi][ni][3] + b1};
                *(float2*)(C + (size_t)r0 * Ncols + col)       = v0;
                *(float2*)(C + (size_t)(r0 + 8) * Ncols + col) = v1;
            }
        }
    }
}

// ---------------- exact fp32 re-rank over candidate list -------------------
// Candidates are a superset of {n : approx_score >= max - MARGIN}; winner is
// always included (MARGIN ~ 13 sigma of each bf16-mma error term). Decision
// uses exact fp32 z.G[n] + c[n] with order-independent argmin-first tie rule.
__global__ void __launch_bounds__(256) rerank_kernel(
        const int* __restrict__ ccnt, const int* __restrict__ cand,
        const float* __restrict__ z, const float* __restrict__ G,
        const float* __restrict__ cvec, int* __restrict__ outIdx) {
    int warp = threadIdx.x >> 5, lane = threadIdx.x & 31;
    int row = blockIdx.x * 8 + warp;

    float zreg[16];
    const float* zr = z + (size_t)row * KD;
    #pragma unroll
    for (int k = 0; k < 16; k++) zreg[k] = zr[lane + 32 * k];

    int nc = ccnt[row];
    float best = -1e30f; int bi = 0x7fffffff;
    if (nc <= NSLOT) {
        for (int c = 0; c < nc; c++) {
            int ci = cand[row * NSLOT + c];
            const float* g = G + (size_t)ci * KD;
            float d = 0.f;
            #pragma unroll
            for (int k = 0; k < 16; k++) d = fmaf(zreg[k], g[lane + 32 * k], d);
            #pragma unroll
            for (int o = 16; o > 0; o >>= 1) d += __shfl_xor_sync(0xffffffffu, d, o);
            d += cvec[ci];
            if (d > best || (d == best && ci < bi)) { best = d; bi = ci; }
        }
    } else {
        // overflow fallback: exact scan of all codes (ascending, strict >)
        for (int ci = 0; ci < NC; ci++) {
            const float* g = G + (size_t)ci * KD;
            float d = 0.f;
            #pragma unroll
            for (int k = 0; k < 16; k++) d = fmaf(zreg[k], g[lane + 32 * k], d);
            #pragma unroll
            for (int o = 16; o > 0; o >>= 1) d += __shfl_xor_sync(0xffffffffu, d, o);
            d += cvec[ci];
            if (d > best) { best = d; bi = ci; }
        }
    }
    if (lane == 0) outIdx[row] = bi;
}

// ---------------- output gather: out[m] = table[idx[m]] --------------------
__global__ void __launch_bounds__(256) gather_out_kernel(
        const float* __restrict__ table, const int* __restrict__ idx,
        float* __restrict__ out) {
    int i = blockIdx.x * 256 + threadIdx.x;
    int m = i >> 7, j = i & 127;
    float4 v = ((const float4*)(table + (size_t)idx[m] * KD))[j];
    ((float4*)(out + (size_t)m * KD))[j] = v;
}

__global__ void idx_out_kernel(const int* __restrict__ idx, float* __restrict__ out) {
    int i = blockIdx.x * 256 + threadIdx.x;
    if (i < M_ROWS) out[i] = (float)idx[i];
}

// ---------------------------------------------------------------------------
extern "C" void kernel_launch(void* const* d_in, const int* in_sizes, int n_in,
                              void* d_out, int out_size) {
    const float* z     = (const float*)d_in[0];
    const float* W_in  = (const float*)d_in[2];
    const float* b_in  = (const float*)d_in[3];
    const float* W_out = (const float*)d_in[4];
    const float* b_out = (const float*)d_in[5];
    const float* emb   = (const float*)d_in[6];
    float* out = (float*)d_out;

    __nv_bfloat16 *z_bf, *e_hi, *e_mid, *e_lo, *wt_hi, *wt_mid, *wt_lo;
    __nv_bfloat16 *wout_hi, *wout_lo, *G_bf;
    float *embn, *G, *cvec, *table;
    unsigned* rowmax;
    int *ccnt, *cand, *idx;
    cudaGetSymbolAddress((void**)&z_bf,   g_z_bf);
    cudaGetSymbolAddress((void**)&embn,   g_embn);
    cudaGetSymbolAddress((void**)&e_hi,   g_e_hi);
    cudaGetSymbolAddress((void**)&e_mid,  g_e_mid);
    cudaGetSymbolAddress((void**)&e_lo,   g_e_lo);
    cudaGetSymbolAddress((void**)&wt_hi,  g_wt_hi);
    cudaGetSymbolAddress((void**)&wt_mid, g_wt_mid);
    cudaGetSymbolAddress((void**)&wt_lo,  g_wt_lo);
    cudaGetSymbolAddress((void**)&wout_hi,g_wout_hi);
    cudaGetSymbolAddress((void**)&wout_lo,g_wout_lo);
    cudaGetSymbolAddress((void**)&G,      g_G);
    cudaGetSymbolAddress((void**)&G_bf,   g_G_bf);
    cudaGetSymbolAddress((void**)&cvec,   g_c);
    cudaGetSymbolAddress((void**)&table,  g_table);
    cudaGetSymbolAddress((void**)&rowmax, g_rowmax);
    cudaGetSymbolAddress((void**)&ccnt,   g_ccnt);
    cudaGetSymbolAddress((void**)&cand,   g_cand);
    cudaGetSymbolAddress((void**)&idx,    g_idx);

    const int SM_T6 = 2 * 6 * 8192;
    const int SM_T3 = 2 * 4 * 8192;
    const int SM_T1 = 2 * 2 * 8192;
    cudaFuncSetAttribute(vq_gemm_kernel<6, false, false>, cudaFuncAttributeMaxDynamicSharedMemorySize, SM_T6);
    cudaFuncSetAttribute(vq_gemm_kernel<1, true,  true >, cudaFuncAttributeMaxDynamicSharedMemorySize, SM_T1);
    cudaFuncSetAttribute(vq_gemm_kernel<3, true,  false>, cudaFuncAttributeMaxDynamicSharedMemorySize, SM_T3);

    // prep
    rownorm_split3_kernel<<<NC, 128>>>(emb, embn, e_hi, e_mid, e_lo);
    transpose_split3_kernel<<<dim3(16, 16), dim3(32, 8)>>>(W_in, wt_hi, wt_mid, wt_lo);
    cvec_kernel<<<NC, 32>>>(embn, b_in, cvec);
    tobf16_kernel<<<2048, 256>>>(z, z_bf, M_ROWS * KD / 4);
    split2_kernel<<<256, 256>>>(W_out, wout_hi, wout_lo, KD * KD / 4);
    zero_state_kernel<<<M_ROWS / 256, 256>>>(rowmax, ccnt);

    // G = embn @ W_in  (fp32-grade via 6-term; tiny: 2048x512x512)
    vq_gemm_kernel<6, false, false><<<dim3(4, 16), 256, SM_T6>>>(
        e_hi, e_mid, e_lo, wt_hi, wt_mid, wt_lo, nullptr, G,
        nullptr, nullptr, nullptr, KD);
    tobf16_kernel<<<256, 256>>>(G, G_bf, NC * KD / 4);

    // code table T = embn @ W_out^T + b_out  (A split = (hi, mid)!)
    vq_gemm_kernel<3, true, false><<<dim3(4, 16), 256, SM_T3>>>(
        e_hi, e_mid, nullptr, wout_hi, wout_lo, nullptr, b_out, table,
        nullptr, nullptr, nullptr, KD);

    // scores GEMM with fused rowmax + candidate push; NO score matrix.
    // grid (M-tiles, N-tiles): one row's 16 CTAs land in different waves.
    vq_gemm_kernel<1, true, true><<<dim3(256, 16), 256, SM_T1>>>(
        z_bf, nullptr, nullptr, G_bf, nullptr, nullptr, cvec,
        nullptr, rowmax, ccnt, cand, NC);

    // warp-per-row exact fp32 re-rank over candidates
    rerank_kernel<<<M_ROWS / 8, 256>>>(ccnt, cand, z, G, cvec, idx);

    // out[m] = table[idx[m]]
    gather_out_kernel<<<M_ROWS * KD / 4 / 256, 256>>>(table, idx, out);

    // indices (as float) in output tail
    if (out_size >= M_ROWS * KD + M_ROWS) {
        idx_out_kernel<<<(M_ROWS + 255) / 256, 256>>>(idx, out + (size_t)M_ROWS * KD);
    }
}